// round 2
// baseline (speedup 1.0000x reference)
#include <cuda_runtime.h>
#include <cstdint>

typedef unsigned long long u64;
typedef unsigned int u32;

#define BATCH 65536
#define NBLK 518
#define PACKF (NBLK * 48)          // 24864 floats (duplicated f32x2 weight pack)
#define NDIFF 514
#define OUT_STAB_OFF (BATCH * 180)

__device__ __align__(16) float g_wpack[PACKF];
__device__ __align__(16) float g_seed[BATCH * 3];
__device__ __align__(16) float g_S3[BATCH * 3];
__device__ __align__(16) float g_M[540];
__device__ u64 g_diff[NDIFF];

// ---------------- f32x2 helpers ----------------
__device__ __forceinline__ u64 pk2(float lo, float hi) {
    u64 r; asm("mov.b64 %0, {%1, %2};" : "=l"(r) : "f"(lo), "f"(hi)); return r;
}
__device__ __forceinline__ void upk2(u64 v, float& lo, float& hi) {
    asm("mov.b64 {%0, %1}, %2;" : "=f"(lo), "=f"(hi) : "l"(v));
}
__device__ __forceinline__ u64 fma2(u64 a, u64 b, u64 c) {
    u64 d; asm("fma.rn.f32x2 %0, %1, %2, %3;" : "=l"(d) : "l"(a), "l"(b), "l"(c)); return d;
}
__device__ __forceinline__ u64 add2(u64 a, u64 b) {
    u64 d; asm("add.rn.f32x2 %0, %1, %2;" : "=l"(d) : "l"(a), "l"(b)); return d;
}
__device__ __forceinline__ u64 tanh2(u64 v) {
    float a, b;
    asm("mov.b64 {%0, %1}, %2;" : "=f"(a), "=f"(b) : "l"(v));
    asm("tanh.approx.f32 %0, %0;" : "+f"(a));
    asm("tanh.approx.f32 %0, %0;" : "+f"(b));
    u64 r;
    asm("mov.b64 %0, {%1, %2};" : "=l"(r) : "f"(a), "f"(b));
    return r;
}
__device__ __forceinline__ float habs(u64 v) {   // |lo| + |hi|  (FADD with |.| operand mods)
    float a, b; upk2(v, a, b); return fabsf(a) + fabsf(b);
}

// ---------------------------------------------------------------------------
// Setup kernel: 258 CTAs x 256 thr.
//   CTAs 0..255 : seed = (L + sin(2piL/3) + sin(...)@Wi)/3 for 256 rows each
//   CTA 256     : rowsums r0,r1,r2 -> fold c into W1, build duplicated pack,
//                 zero g_diff
//   CTA 257     : rowsum r3 -> M[3,180] = sum_i r3[i]*W_final[3i+f, :]
// ---------------------------------------------------------------------------
__global__ void __launch_bounds__(256) setup_kernel(
    const float* __restrict__ x,  const float* __restrict__ Wl, const float* __restrict__ Wi,
    const float* __restrict__ W1_0, const float* __restrict__ b1_0,
    const float* __restrict__ W2_0, const float* __restrict__ b2_0, const float* __restrict__ R0,
    const float* __restrict__ W1_1, const float* __restrict__ b1_1,
    const float* __restrict__ W2_1, const float* __restrict__ b2_1, const float* __restrict__ R1,
    const float* __restrict__ W1_2, const float* __restrict__ b1_2,
    const float* __restrict__ W2_2, const float* __restrict__ b2_2, const float* __restrict__ R2,
    const float* __restrict__ W1_3, const float* __restrict__ b1_3,
    const float* __restrict__ W2_3, const float* __restrict__ b2_3, const float* __restrict__ R3,
    const float* __restrict__ Wf)
{
    extern __shared__ float smem[];
    const int tid = threadIdx.x;
    const int bid = blockIdx.x;

    if (bid < 256) {
        // ---- seed ----
        float* sx = smem;                       // 256 rows x pitch 93
        const int base = bid * 256;
        const float* xg = x + (size_t)base * 90;
        for (int e = tid; e < 256 * 90; e += 256) {
            int r = e / 90;
            int k = e - r * 90;
            sx[r * 93 + k] = xg[e];
        }
        __syncthreads();
        const float* xr = sx + tid * 93;
        float L0 = 0.f, L1 = 0.f, L2 = 0.f;
        #pragma unroll 6
        for (int k = 0; k < 90; k++) {
            float xv = xr[k];
            L0 = fmaf(xv, __ldg(&Wl[k * 3 + 0]), L0);
            L1 = fmaf(xv, __ldg(&Wl[k * 3 + 1]), L1);
            L2 = fmaf(xv, __ldg(&Wl[k * 3 + 2]), L2);
        }
        const float C = 2.0943951023931953f;   // 2*pi/3
        float E0 = sinf(C * L0), E1 = sinf(C * L1), E2 = sinf(C * L2);
        float I0 = E0 * __ldg(&Wi[0]) + E1 * __ldg(&Wi[3]) + E2 * __ldg(&Wi[6]);
        float I1 = E0 * __ldg(&Wi[1]) + E1 * __ldg(&Wi[4]) + E2 * __ldg(&Wi[7]);
        float I2 = E0 * __ldg(&Wi[2]) + E1 * __ldg(&Wi[5]) + E2 * __ldg(&Wi[8]);
        const float TH = 1.0f / 3.0f;
        int row = base + tid;
        g_seed[row * 3 + 0] = (L0 + E0 + I0) * TH;
        g_seed[row * 3 + 1] = (L1 + E1 + I1) * TH;
        g_seed[row * 3 + 2] = (L2 + E2 + I2) * TH;
    } else if (bid == 256) {
        // ---- rowsums r0,r1,r2 + weight pack + zero diffs ----
        __shared__ float rs[86];                // r0[0..1] r1[2..13] r2[14..85]
        int wid = tid >> 5, lane = tid & 31;
        for (int rr = wid; rr < 86; rr += 8) {
            const float* Rp; int n, row;
            if (rr < 2)       { Rp = R0; n = 2;  row = rr; }
            else if (rr < 14) { Rp = R1; n = 12; row = rr - 2; }
            else              { Rp = R2; n = 72; row = rr - 14; }
            float s = 0.f;
            for (int kk = lane; kk < n; kk += 32) s += Rp[row * n + kk];
            #pragma unroll
            for (int o = 16; o; o >>= 1) s += __shfl_xor_sync(0xffffffffu, s, o);
            if (lane == 0) rs[rr] = s;
        }
        __syncthreads();
        for (int i = tid; i < NDIFF; i += 256) g_diff[i] = 0ull;
        for (int e = tid; e < NBLK * 24; e += 256) {
            int blk = e / 24, k = e - blk * 24;
            int l, j;
            if (blk < 2)       { l = 0; j = blk; }
            else if (blk < 14) { l = 1; j = blk - 2; }
            else if (blk < 86) { l = 2; j = blk - 14; }
            else               { l = 3; j = blk - 86; }
            float c = 1.f;
            if (l == 1)      c = rs[0 + (j & 1)];
            else if (l == 2) c = rs[2 + (j % 12)];
            else if (l == 3) c = rs[14 + (j % 72)];
            const float *W1p, *B1p, *W2p, *B2p;
            if (l == 0)      { W1p = W1_0; B1p = b1_0; W2p = W2_0; B2p = b2_0; }
            else if (l == 1) { W1p = W1_1; B1p = b1_1; W2p = W2_1; B2p = b2_1; }
            else if (l == 2) { W1p = W1_2; B1p = b1_2; W2p = W2_2; B2p = b2_2; }
            else             { W1p = W1_3; B1p = b1_3; W2p = W2_3; B2p = b2_3; }
            float v;
            if (k < 9)       v = c * W1p[j * 9 + k];
            else if (k < 12) v = B1p[j * 3 + (k - 9)];
            else if (k < 21) v = W2p[j * 9 + (k - 12)];
            else             v = B2p[j * 3 + (k - 21)];
            g_wpack[2 * e]     = v;
            g_wpack[2 * e + 1] = v;
        }
    } else {
        // ---- r3 + M ----
        __shared__ float r3s[432];
        int wid = tid >> 5, lane = tid & 31;
        for (int row = wid; row < 432; row += 8) {
            float s = 0.f;
            for (int kk = lane; kk < 432; kk += 32) s += R3[row * 432 + kk];
            #pragma unroll
            for (int o = 16; o; o >>= 1) s += __shfl_xor_sync(0xffffffffu, s, o);
            if (lane == 0) r3s[row] = s;
        }
        __syncthreads();
        for (int oo = tid; oo < 540; oo += 256) {
            int f = oo / 180, o = oo - f * 180;
            float acc = 0.f;
            for (int i = 0; i < 432; i++)
                acc = fmaf(r3s[i], __ldg(&Wf[(3 * i + f) * 180 + o]), acc);
            g_M[oo] = acc;
        }
    }
}

// ---------------------------------------------------------------------------
// Main kernel: 128 CTAs x 128 thr, 4 batch elems/thread (2 f32x2 pairs).
// Cascade of 518 blocks on a 3-vector S, diffs via fixed-point REDUX + RED.
// ---------------------------------------------------------------------------
__global__ void __launch_bounds__(128) main_kernel() {
    extern __shared__ u64 sw[];
    {
        const float4* src = (const float4*)g_wpack;
        float4* dst = (float4*)sw;
        for (int i = threadIdx.x; i < PACKF / 4; i += 128) dst[i] = src[i];
    }
    __syncthreads();

    const int T = blockIdx.x * 128 + threadIdx.x;
    const float4* sp = (const float4*)g_seed + 3 * T;
    float4 v0 = sp[0], v1 = sp[1], v2 = sp[2];
    // rows 4T..4T+3; pair A = rows (4T,4T+1), pair B = rows (4T+2,4T+3)
    u64 SA0 = pk2(v0.x, v0.w), SA1 = pk2(v0.y, v1.x), SA2 = pk2(v0.z, v1.y);
    u64 SB0 = pk2(v1.z, v2.y), SB1 = pk2(v1.w, v2.z), SB2 = pk2(v2.x, v2.w);

    const u64 NEG1 = 0xBF800000BF800000ull;   // (-1.f, -1.f)
    const u64* w = sw;
    int didx = 0;
    const int lane = threadIdx.x & 31;
    const int nbl[4] = {2, 12, 72, 432};

    #pragma unroll
    for (int l = 0; l < 4; l++) {
        u64 aA0 = 0, aA1 = 0, aA2 = 0, aB0 = 0, aB1 = 0, aB2 = 0;
        u64 pA0 = 0, pA1 = 0, pA2 = 0, pB0 = 0, pB1 = 0, pB2 = 0;
        const int n = nbl[l];
        #pragma unroll 2
        for (int j = 0; j < n; j++) {
            u64 w0 = w[0], w1 = w[1], w2 = w[2], w3 = w[3], w4 = w[4],
                w5 = w[5], w6 = w[6], w7 = w[7], w8 = w[8];
            u64 c0 = w[9], c1 = w[10], c2 = w[11];
            u64 hA0 = fma2(SA0, w0, fma2(SA1, w3, fma2(SA2, w6, c0)));
            u64 hA1 = fma2(SA0, w1, fma2(SA1, w4, fma2(SA2, w7, c1)));
            u64 hA2 = fma2(SA0, w2, fma2(SA1, w5, fma2(SA2, w8, c2)));
            u64 hB0 = fma2(SB0, w0, fma2(SB1, w3, fma2(SB2, w6, c0)));
            u64 hB1 = fma2(SB0, w1, fma2(SB1, w4, fma2(SB2, w7, c1)));
            u64 hB2 = fma2(SB0, w2, fma2(SB1, w5, fma2(SB2, w8, c2)));
            hA0 = tanh2(hA0); hA1 = tanh2(hA1); hA2 = tanh2(hA2);
            hB0 = tanh2(hB0); hB1 = tanh2(hB1); hB2 = tanh2(hB2);
            u64 u0 = w[12], u1 = w[13], u2 = w[14], u3 = w[15], u4 = w[16],
                u5 = w[17], u6 = w[18], u7 = w[19], u8 = w[20];
            u64 d0 = w[21], d1 = w[22], d2 = w[23];
            u64 oA0 = fma2(hA0, u0, fma2(hA1, u3, fma2(hA2, u6, d0)));
            u64 oA1 = fma2(hA0, u1, fma2(hA1, u4, fma2(hA2, u7, d1)));
            u64 oA2 = fma2(hA0, u2, fma2(hA1, u5, fma2(hA2, u8, d2)));
            u64 oB0 = fma2(hB0, u0, fma2(hB1, u3, fma2(hB2, u6, d0)));
            u64 oB1 = fma2(hB0, u1, fma2(hB1, u4, fma2(hB2, u7, d1)));
            u64 oB2 = fma2(hB0, u2, fma2(hB1, u5, fma2(hB2, u8, d2)));
            aA0 = add2(aA0, oA0); aA1 = add2(aA1, oA1); aA2 = add2(aA2, oA2);
            aB0 = add2(aB0, oB0); aB1 = add2(aB1, oB1); aB2 = add2(aB2, oB2);
            if (j) {
                u64 e0 = fma2(pA0, NEG1, oA0), e1 = fma2(pA1, NEG1, oA1),
                    e2 = fma2(pA2, NEG1, oA2), e3 = fma2(pB0, NEG1, oB0),
                    e4 = fma2(pB1, NEG1, oB1), e5 = fma2(pB2, NEG1, oB2);
                float ds = ((habs(e0) + habs(e1)) + (habs(e2) + habs(e3))) +
                           (habs(e4) + habs(e5));
                u32 fx = __float2uint_rn(ds * 65536.0f);
                fx = __reduce_add_sync(0xffffffffu, fx);
                if (lane == 0) atomicAdd(&g_diff[didx], (u64)fx);
                didx++;
            }
            pA0 = oA0; pA1 = oA1; pA2 = oA2;
            pB0 = oB0; pB1 = oB1; pB2 = oB2;
            w += 24;
        }
        SA0 = aA0; SA1 = aA1; SA2 = aA2;
        SB0 = aB0; SB1 = aB1; SB2 = aB2;
    }

    float a0l, a0h, a1l, a1h, a2l, a2h, b0l, b0h, b1l, b1h, b2l, b2h;
    upk2(SA0, a0l, a0h); upk2(SA1, a1l, a1h); upk2(SA2, a2l, a2h);
    upk2(SB0, b0l, b0h); upk2(SB1, b1l, b1h); upk2(SB2, b2l, b2h);
    float4* op = (float4*)g_S3 + 3 * T;
    op[0] = make_float4(a0l, a1l, a2l, a0h);
    op[1] = make_float4(a1h, a2h, b0l, b1l);
    op[2] = make_float4(b2l, b0h, b1h, b2h);
}

// ---------------------------------------------------------------------------
// Epilogue: out[b,:] = S3[b,:] @ M + b_final (coalesced float4 stores),
// block 0 additionally converts diff accumulators into the 518 stab outputs.
// ---------------------------------------------------------------------------
__global__ void __launch_bounds__(256) out_kernel(const float* __restrict__ bfin,
                                                  float* __restrict__ out) {
    if (blockIdx.x == 0) {
        for (int s = threadIdx.x; s < NBLK; s += 256) {
            int l = (s >= 86) ? 3 : (s >= 14) ? 2 : (s >= 2) ? 1 : 0;
            const int sbase[4] = {0, 2, 14, 86};
            float val = 1.0f;
            if (s != sbase[l]) {
                double mean = (double)g_diff[s - l - 1] * (1.0 / (65536.0 * 196608.0));
                double v = 1.0 - mean;
                val = (float)(v > 0.0 ? v : 0.0);
            }
            out[OUT_STAB_OFF + s] = val;
        }
    }
    int idx = blockIdx.x * 256 + threadIdx.x;          // 0 .. 65536*45-1
    int b = idx / 45;
    int c = idx - b * 45;
    float s0 = __ldg(&g_S3[b * 3 + 0]);
    float s1 = __ldg(&g_S3[b * 3 + 1]);
    float s2 = __ldg(&g_S3[b * 3 + 2]);
    float4 m0 = __ldg((const float4*)(g_M + 4 * c));
    float4 m1 = __ldg((const float4*)(g_M + 180 + 4 * c));
    float4 m2 = __ldg((const float4*)(g_M + 360 + 4 * c));
    float4 bf = __ldg((const float4*)(bfin + 4 * c));
    float4 r;
    r.x = fmaf(s0, m0.x, fmaf(s1, m1.x, fmaf(s2, m2.x, bf.x)));
    r.y = fmaf(s0, m0.y, fmaf(s1, m1.y, fmaf(s2, m2.y, bf.y)));
    r.z = fmaf(s0, m0.z, fmaf(s1, m1.z, fmaf(s2, m2.z, bf.z)));
    r.w = fmaf(s0, m0.w, fmaf(s1, m1.w, fmaf(s2, m2.w, bf.w)));
    ((float4*)out)[idx] = r;
}

extern "C" void kernel_launch(void* const* d_in, const int* in_sizes, int n_in,
                              void* d_out, int out_size) {
    const float* x    = (const float*)d_in[0];
    const float* Wl   = (const float*)d_in[1];
    const float* Wi   = (const float*)d_in[2];
    const float* W1_0 = (const float*)d_in[3];
    const float* b1_0 = (const float*)d_in[4];
    const float* W2_0 = (const float*)d_in[5];
    const float* b2_0 = (const float*)d_in[6];
    const float* R0   = (const float*)d_in[7];
    const float* W1_1 = (const float*)d_in[8];
    const float* b1_1 = (const float*)d_in[9];
    const float* W2_1 = (const float*)d_in[10];
    const float* b2_1 = (const float*)d_in[11];
    const float* R1   = (const float*)d_in[12];
    const float* W1_2 = (const float*)d_in[13];
    const float* b1_2 = (const float*)d_in[14];
    const float* W2_2 = (const float*)d_in[15];
    const float* b2_2 = (const float*)d_in[16];
    const float* R2   = (const float*)d_in[17];
    const float* W1_3 = (const float*)d_in[18];
    const float* b1_3 = (const float*)d_in[19];
    const float* W2_3 = (const float*)d_in[20];
    const float* b2_3 = (const float*)d_in[21];
    const float* R3   = (const float*)d_in[22];
    const float* Wf   = (const float*)d_in[23];
    const float* bf   = (const float*)d_in[24];

    cudaFuncSetAttribute(setup_kernel, cudaFuncAttributeMaxDynamicSharedMemorySize, 256 * 93 * 4);
    cudaFuncSetAttribute(main_kernel,  cudaFuncAttributeMaxDynamicSharedMemorySize, PACKF * 4);

    setup_kernel<<<258, 256, 256 * 93 * 4>>>(
        x, Wl, Wi,
        W1_0, b1_0, W2_0, b2_0, R0,
        W1_1, b1_1, W2_1, b2_1, R1,
        W1_2, b1_2, W2_2, b2_2, R2,
        W1_3, b1_3, W2_3, b2_3, R3,
        Wf);
    main_kernel<<<128, 128, PACKF * 4>>>();
    out_kernel<<<BATCH * 45 / 256, 256>>>(bf, (float*)d_out);
}

// round 3
// speedup vs baseline: 1.1790x; 1.1790x over previous
#include <cuda_runtime.h>
#include <cstdint>

typedef unsigned long long u64;
typedef unsigned int u32;

#define BATCH 65536
#define NBLK 518
#define PACKF (NBLK * 48)          // 24864 floats (duplicated f32x2 weight pack)
#define NDIFF 514
#define OUT_STAB_OFF (BATCH * 180)

__device__ __align__(16) float g_wpack[PACKF];
__device__ __align__(16) float g_seed[BATCH * 3];
__device__ __align__(16) float g_S3[BATCH * 3];
__device__ __align__(16) float g_M[540];
__device__ float g_rs[86];          // rowsums of R0 (2), R1 (12), R2 (72)
__device__ float g_rs3[432];        // rowsums of R3
__device__ u64 g_diff[NDIFF];

// ---------------- f32x2 helpers ----------------
__device__ __forceinline__ u64 pk2(float lo, float hi) {
    u64 r; asm("mov.b64 %0, {%1, %2};" : "=l"(r) : "f"(lo), "f"(hi)); return r;
}
__device__ __forceinline__ void upk2(u64 v, float& lo, float& hi) {
    asm("mov.b64 {%0, %1}, %2;" : "=f"(lo), "=f"(hi) : "l"(v));
}
__device__ __forceinline__ u64 fma2(u64 a, u64 b, u64 c) {
    u64 d; asm("fma.rn.f32x2 %0, %1, %2, %3;" : "=l"(d) : "l"(a), "l"(b), "l"(c)); return d;
}
__device__ __forceinline__ u64 add2(u64 a, u64 b) {
    u64 d; asm("add.rn.f32x2 %0, %1, %2;" : "=l"(d) : "l"(a), "l"(b)); return d;
}
__device__ __forceinline__ u64 tanh2(u64 v) {
    float a, b;
    asm("mov.b64 {%0, %1}, %2;" : "=f"(a), "=f"(b) : "l"(v));
    asm("tanh.approx.f32 %0, %0;" : "+f"(a));
    asm("tanh.approx.f32 %0, %0;" : "+f"(b));
    u64 r;
    asm("mov.b64 %0, {%1, %2};" : "=l"(r) : "f"(a), "f"(b));
    return r;
}
__device__ __forceinline__ float habs(u64 v) {   // |lo| + |hi|
    float a, b; upk2(v, a, b); return fabsf(a) + fabsf(b);
}

// ---------------------------------------------------------------------------
// s1: 621 CTAs x 128 thr.
//   CTAs 0..511  : seed for 128 rows each (x + W_logic staged in smem, float4)
//   CTA 512      : rowsums r0,r1,r2 -> g_rs; zero g_diff, g_M
//   CTAs 513..620: rowsums of R3 (warp per row, 4 rows/CTA) -> g_rs3
// ---------------------------------------------------------------------------
#define SEED_CTAS 512
#define S1_SMEM (128 * 46 * 8 + 276 * 4)   // x: 128 rows x 46 float2 ; w: 276 f

__global__ void __launch_bounds__(128) s1_kernel(
    const float* __restrict__ x,  const float* __restrict__ Wl, const float* __restrict__ Wi,
    const float* __restrict__ R0, const float* __restrict__ R1,
    const float* __restrict__ R2, const float* __restrict__ R3)
{
    extern __shared__ float2 s_x2[];
    const int tid = threadIdx.x;
    const int bid = blockIdx.x;

    if (bid < SEED_CTAS) {
        float* s_w = (float*)(s_x2 + 128 * 46);     // 276 floats (270 + zero pad)
        const int base = bid * 128;
        // stage x rows (coalesced float2), pitch 46 float2 (= 92 floats)
        const float2* xg = (const float2*)(x + (size_t)base * 90);
        for (int e = tid; e < 128 * 45; e += 128) {
            int r = e / 45;
            int k = e - r * 45;
            s_x2[r * 46 + k] = xg[e];
        }
        s_x2[tid * 46 + 45] = make_float2(0.f, 0.f);   // zero pad per row
        // stage W_logic (270 floats) padded to 276 with zeros
        for (int i = tid; i < 138; i += 128) {
            float2 v = make_float2(0.f, 0.f);
            if (i < 135) v = ((const float2*)Wl)[i];
            ((float2*)s_w)[i] = v;
        }
        __syncthreads();

        const float4* xr  = (const float4*)s_x2 + tid * 23;   // 92 floats = 23 f4
        const float4* w4  = (const float4*)s_w;
        float L0 = 0.f, L1 = 0.f, L2 = 0.f;
        #pragma unroll
        for (int c = 0; c < 23; c++) {
            float4 xv = xr[c];
            float4 w0 = w4[3 * c], w1 = w4[3 * c + 1], w2 = w4[3 * c + 2];
            L0 = fmaf(xv.x, w0.x, L0); L1 = fmaf(xv.x, w0.y, L1); L2 = fmaf(xv.x, w0.z, L2);
            L0 = fmaf(xv.y, w0.w, L0); L1 = fmaf(xv.y, w1.x, L1); L2 = fmaf(xv.y, w1.y, L2);
            L0 = fmaf(xv.z, w1.z, L0); L1 = fmaf(xv.z, w1.w, L1); L2 = fmaf(xv.z, w2.x, L2);
            L0 = fmaf(xv.w, w2.y, L0); L1 = fmaf(xv.w, w2.z, L1); L2 = fmaf(xv.w, w2.w, L2);
        }
        const float C = 2.0943951023931953f;   // 2*pi/3
        float E0 = sinf(C * L0), E1 = sinf(C * L1), E2 = sinf(C * L2);
        float I0 = E0 * __ldg(&Wi[0]) + E1 * __ldg(&Wi[3]) + E2 * __ldg(&Wi[6]);
        float I1 = E0 * __ldg(&Wi[1]) + E1 * __ldg(&Wi[4]) + E2 * __ldg(&Wi[7]);
        float I2 = E0 * __ldg(&Wi[2]) + E1 * __ldg(&Wi[5]) + E2 * __ldg(&Wi[8]);
        const float TH = 1.0f / 3.0f;
        int row = base + tid;
        g_seed[row * 3 + 0] = (L0 + E0 + I0) * TH;
        g_seed[row * 3 + 1] = (L1 + E1 + I1) * TH;
        g_seed[row * 3 + 2] = (L2 + E2 + I2) * TH;
    } else if (bid == SEED_CTAS) {
        // rowsums r0,r1,r2 (warp per row, 4 warps stride)
        int wid = tid >> 5, lane = tid & 31;
        for (int rr = wid; rr < 86; rr += 4) {
            const float* Rp; int n, row;
            if (rr < 2)       { Rp = R0; n = 2;  row = rr; }
            else if (rr < 14) { Rp = R1; n = 12; row = rr - 2; }
            else              { Rp = R2; n = 72; row = rr - 14; }
            float s = 0.f;
            for (int kk = lane; kk < n; kk += 32) s += Rp[row * n + kk];
            #pragma unroll
            for (int o = 16; o; o >>= 1) s += __shfl_xor_sync(0xffffffffu, s, o);
            if (lane == 0) g_rs[rr] = s;
        }
        for (int i = tid; i < NDIFF; i += 128) g_diff[i] = 0ull;
        for (int i = tid; i < 540; i += 128) g_M[i] = 0.f;
    } else {
        // R3 rowsums: 108 CTAs x 4 warps = 432 rows
        int wid = tid >> 5, lane = tid & 31;
        int row = (bid - SEED_CTAS - 1) * 4 + wid;
        const float* Rp = R3 + row * 432;
        float s = 0.f;
        #pragma unroll 7
        for (int kk = lane; kk < 432; kk += 32) s += Rp[kk];
        #pragma unroll
        for (int o = 16; o; o >>= 1) s += __shfl_xor_sync(0xffffffffu, s, o);
        if (lane == 0) g_rs3[row] = s;
    }
}

// ---------------------------------------------------------------------------
// s2: 13 CTAs x 256 thr.
//   CTAs 0..8 : M partials over 48 i-indices each (coalesced Wf reads + atomics)
//   CTAs 9..12: duplicated f32x2 weight pack (c folded into W1)
// ---------------------------------------------------------------------------
__global__ void __launch_bounds__(256) s2_kernel(
    const float* __restrict__ Wf,
    const float* __restrict__ W1_0, const float* __restrict__ b1_0,
    const float* __restrict__ W2_0, const float* __restrict__ b2_0,
    const float* __restrict__ W1_1, const float* __restrict__ b1_1,
    const float* __restrict__ W2_1, const float* __restrict__ b2_1,
    const float* __restrict__ W1_2, const float* __restrict__ b1_2,
    const float* __restrict__ W2_2, const float* __restrict__ b2_2,
    const float* __restrict__ W1_3, const float* __restrict__ b1_3,
    const float* __restrict__ W2_3, const float* __restrict__ b2_3)
{
    const int tid = threadIdx.x;
    const int bid = blockIdx.x;

    if (bid < 9) {
        __shared__ float r3c[48];
        const int i0 = bid * 48;
        if (tid < 48) r3c[tid] = g_rs3[i0 + tid];
        __syncthreads();
        if (tid < 180) {
            float a0 = 0.f, a1 = 0.f, a2 = 0.f;
            const float* basep = Wf + (size_t)(3 * i0) * 180 + tid;
            #pragma unroll 4
            for (int ii = 0; ii < 48; ii++) {
                float rv = r3c[ii];
                a0 = fmaf(rv, __ldg(basep + (3 * ii + 0) * 180), a0);
                a1 = fmaf(rv, __ldg(basep + (3 * ii + 1) * 180), a1);
                a2 = fmaf(rv, __ldg(basep + (3 * ii + 2) * 180), a2);
            }
            atomicAdd(&g_M[0 * 180 + tid], a0);
            atomicAdd(&g_M[1 * 180 + tid], a1);
            atomicAdd(&g_M[2 * 180 + tid], a2);
        }
    } else {
        for (int e = (bid - 9) * 256 + tid; e < NBLK * 24; e += 4 * 256) {
            int blk = e / 24, k = e - blk * 24;
            int l, j;
            if (blk < 2)       { l = 0; j = blk; }
            else if (blk < 14) { l = 1; j = blk - 2; }
            else if (blk < 86) { l = 2; j = blk - 14; }
            else               { l = 3; j = blk - 86; }
            float c = 1.f;
            if (l == 1)      c = __ldg(&g_rs[0 + (j & 1)]);
            else if (l == 2) c = __ldg(&g_rs[2 + (j % 12)]);
            else if (l == 3) c = __ldg(&g_rs[14 + (j % 72)]);
            const float *W1p, *B1p, *W2p, *B2p;
            if (l == 0)      { W1p = W1_0; B1p = b1_0; W2p = W2_0; B2p = b2_0; }
            else if (l == 1) { W1p = W1_1; B1p = b1_1; W2p = W2_1; B2p = b2_1; }
            else if (l == 2) { W1p = W1_2; B1p = b1_2; W2p = W2_2; B2p = b2_2; }
            else             { W1p = W1_3; B1p = b1_3; W2p = W2_3; B2p = b2_3; }
            float v;
            if (k < 9)       v = c * W1p[j * 9 + k];
            else if (k < 12) v = B1p[j * 3 + (k - 9)];
            else if (k < 21) v = W2p[j * 9 + (k - 12)];
            else             v = B2p[j * 3 + (k - 21)];
            g_wpack[2 * e]     = v;
            g_wpack[2 * e + 1] = v;
        }
    }
}

// ---------------------------------------------------------------------------
// Main kernel: 128 CTAs x 128 thr, 4 batch elems/thread (2 f32x2 pairs).
// Cascade of 518 blocks on a 3-vector S, diffs via fixed-point REDUX + RED.
// ---------------------------------------------------------------------------
__global__ void __launch_bounds__(128) main_kernel() {
    extern __shared__ u64 sw[];
    {
        const float4* src = (const float4*)g_wpack;
        float4* dst = (float4*)sw;
        for (int i = threadIdx.x; i < PACKF / 4; i += 128) dst[i] = src[i];
    }
    __syncthreads();

    const int T = blockIdx.x * 128 + threadIdx.x;
    const float4* sp = (const float4*)g_seed + 3 * T;
    float4 v0 = sp[0], v1 = sp[1], v2 = sp[2];
    // rows 4T..4T+3; pair A = rows (4T,4T+1), pair B = rows (4T+2,4T+3)
    u64 SA0 = pk2(v0.x, v0.w), SA1 = pk2(v0.y, v1.x), SA2 = pk2(v0.z, v1.y);
    u64 SB0 = pk2(v1.z, v2.y), SB1 = pk2(v1.w, v2.z), SB2 = pk2(v2.x, v2.w);

    const u64 NEG1 = 0xBF800000BF800000ull;   // (-1.f, -1.f)
    const u64* w = sw;
    int didx = 0;
    const int lane = threadIdx.x & 31;
    const int nbl[4] = {2, 12, 72, 432};

    #pragma unroll
    for (int l = 0; l < 4; l++) {
        u64 aA0 = 0, aA1 = 0, aA2 = 0, aB0 = 0, aB1 = 0, aB2 = 0;
        u64 pA0 = 0, pA1 = 0, pA2 = 0, pB0 = 0, pB1 = 0, pB2 = 0;
        const int n = nbl[l];
        #pragma unroll 2
        for (int j = 0; j < n; j++) {
            u64 w0 = w[0], w1 = w[1], w2 = w[2], w3 = w[3], w4 = w[4],
                w5 = w[5], w6 = w[6], w7 = w[7], w8 = w[8];
            u64 c0 = w[9], c1 = w[10], c2 = w[11];
            u64 hA0 = fma2(SA0, w0, fma2(SA1, w3, fma2(SA2, w6, c0)));
            u64 hA1 = fma2(SA0, w1, fma2(SA1, w4, fma2(SA2, w7, c1)));
            u64 hA2 = fma2(SA0, w2, fma2(SA1, w5, fma2(SA2, w8, c2)));
            u64 hB0 = fma2(SB0, w0, fma2(SB1, w3, fma2(SB2, w6, c0)));
            u64 hB1 = fma2(SB0, w1, fma2(SB1, w4, fma2(SB2, w7, c1)));
            u64 hB2 = fma2(SB0, w2, fma2(SB1, w5, fma2(SB2, w8, c2)));
            hA0 = tanh2(hA0); hA1 = tanh2(hA1); hA2 = tanh2(hA2);
            hB0 = tanh2(hB0); hB1 = tanh2(hB1); hB2 = tanh2(hB2);
            u64 u0 = w[12], u1 = w[13], u2 = w[14], u3 = w[15], u4 = w[16],
                u5 = w[17], u6 = w[18], u7 = w[19], u8 = w[20];
            u64 d0 = w[21], d1 = w[22], d2 = w[23];
            u64 oA0 = fma2(hA0, u0, fma2(hA1, u3, fma2(hA2, u6, d0)));
            u64 oA1 = fma2(hA0, u1, fma2(hA1, u4, fma2(hA2, u7, d1)));
            u64 oA2 = fma2(hA0, u2, fma2(hA1, u5, fma2(hA2, u8, d2)));
            u64 oB0 = fma2(hB0, u0, fma2(hB1, u3, fma2(hB2, u6, d0)));
            u64 oB1 = fma2(hB0, u1, fma2(hB1, u4, fma2(hB2, u7, d1)));
            u64 oB2 = fma2(hB0, u2, fma2(hB1, u5, fma2(hB2, u8, d2)));
            aA0 = add2(aA0, oA0); aA1 = add2(aA1, oA1); aA2 = add2(aA2, oA2);
            aB0 = add2(aB0, oB0); aB1 = add2(aB1, oB1); aB2 = add2(aB2, oB2);
            if (j) {
                u64 e0 = fma2(pA0, NEG1, oA0), e1 = fma2(pA1, NEG1, oA1),
                    e2 = fma2(pA2, NEG1, oA2), e3 = fma2(pB0, NEG1, oB0),
                    e4 = fma2(pB1, NEG1, oB1), e5 = fma2(pB2, NEG1, oB2);
                float ds = ((habs(e0) + habs(e1)) + (habs(e2) + habs(e3))) +
                           (habs(e4) + habs(e5));
                u32 fx = __float2uint_rn(ds * 65536.0f);
                fx = __reduce_add_sync(0xffffffffu, fx);
                if (lane == 0) atomicAdd(&g_diff[didx], (u64)fx);
                didx++;
            }
            pA0 = oA0; pA1 = oA1; pA2 = oA2;
            pB0 = oB0; pB1 = oB1; pB2 = oB2;
            w += 24;
        }
        SA0 = aA0; SA1 = aA1; SA2 = aA2;
        SB0 = aB0; SB1 = aB1; SB2 = aB2;
    }

    float a0l, a0h, a1l, a1h, a2l, a2h, b0l, b0h, b1l, b1h, b2l, b2h;
    upk2(SA0, a0l, a0h); upk2(SA1, a1l, a1h); upk2(SA2, a2l, a2h);
    upk2(SB0, b0l, b0h); upk2(SB1, b1l, b1h); upk2(SB2, b2l, b2h);
    float4* op = (float4*)g_S3 + 3 * T;
    op[0] = make_float4(a0l, a1l, a2l, a0h);
    op[1] = make_float4(a1h, a2h, b0l, b1l);
    op[2] = make_float4(b2l, b0h, b1h, b2h);
}

// ---------------------------------------------------------------------------
// Epilogue: out[b,:] = S3[b,:] @ M + b_final (coalesced float4 stores),
// block 0 additionally converts diff accumulators into the 518 stab outputs.
// ---------------------------------------------------------------------------
__global__ void __launch_bounds__(256) out_kernel(const float* __restrict__ bfin,
                                                  float* __restrict__ out) {
    if (blockIdx.x == 0) {
        for (int s = threadIdx.x; s < NBLK; s += 256) {
            int l = (s >= 86) ? 3 : (s >= 14) ? 2 : (s >= 2) ? 1 : 0;
            const int sbase[4] = {0, 2, 14, 86};
            float val = 1.0f;
            if (s != sbase[l]) {
                double mean = (double)g_diff[s - l - 1] * (1.0 / (65536.0 * 196608.0));
                double v = 1.0 - mean;
                val = (float)(v > 0.0 ? v : 0.0);
            }
            out[OUT_STAB_OFF + s] = val;
        }
    }
    int idx = blockIdx.x * 256 + threadIdx.x;          // 0 .. 65536*45-1
    int b = idx / 45;
    int c = idx - b * 45;
    float s0 = __ldg(&g_S3[b * 3 + 0]);
    float s1 = __ldg(&g_S3[b * 3 + 1]);
    float s2 = __ldg(&g_S3[b * 3 + 2]);
    float4 m0 = __ldg((const float4*)(g_M + 4 * c));
    float4 m1 = __ldg((const float4*)(g_M + 180 + 4 * c));
    float4 m2 = __ldg((const float4*)(g_M + 360 + 4 * c));
    float4 bf = __ldg((const float4*)(bfin + 4 * c));
    float4 r;
    r.x = fmaf(s0, m0.x, fmaf(s1, m1.x, fmaf(s2, m2.x, bf.x)));
    r.y = fmaf(s0, m0.y, fmaf(s1, m1.y, fmaf(s2, m2.y, bf.y)));
    r.z = fmaf(s0, m0.z, fmaf(s1, m1.z, fmaf(s2, m2.z, bf.z)));
    r.w = fmaf(s0, m0.w, fmaf(s1, m1.w, fmaf(s2, m2.w, bf.w)));
    ((float4*)out)[idx] = r;
}

extern "C" void kernel_launch(void* const* d_in, const int* in_sizes, int n_in,
                              void* d_out, int out_size) {
    const float* x    = (const float*)d_in[0];
    const float* Wl   = (const float*)d_in[1];
    const float* Wi   = (const float*)d_in[2];
    const float* W1_0 = (const float*)d_in[3];
    const float* b1_0 = (const float*)d_in[4];
    const float* W2_0 = (const float*)d_in[5];
    const float* b2_0 = (const float*)d_in[6];
    const float* R0   = (const float*)d_in[7];
    const float* W1_1 = (const float*)d_in[8];
    const float* b1_1 = (const float*)d_in[9];
    const float* W2_1 = (const float*)d_in[10];
    const float* b2_1 = (const float*)d_in[11];
    const float* R1   = (const float*)d_in[12];
    const float* W1_2 = (const float*)d_in[13];
    const float* b1_2 = (const float*)d_in[14];
    const float* W2_2 = (const float*)d_in[15];
    const float* b2_2 = (const float*)d_in[16];
    const float* R2   = (const float*)d_in[17];
    const float* W1_3 = (const float*)d_in[18];
    const float* b1_3 = (const float*)d_in[19];
    const float* W2_3 = (const float*)d_in[20];
    const float* b2_3 = (const float*)d_in[21];
    const float* R3   = (const float*)d_in[22];
    const float* Wf   = (const float*)d_in[23];
    const float* bf   = (const float*)d_in[24];

    cudaFuncSetAttribute(main_kernel, cudaFuncAttributeMaxDynamicSharedMemorySize, PACKF * 4);

    s1_kernel<<<SEED_CTAS + 1 + 108, 128, S1_SMEM>>>(x, Wl, Wi, R0, R1, R2, R3);
    s2_kernel<<<13, 256>>>(Wf,
        W1_0, b1_0, W2_0, b2_0,
        W1_1, b1_1, W2_1, b2_1,
        W1_2, b1_2, W2_2, b2_2,
        W1_3, b1_3, W2_3, b2_3);
    main_kernel<<<128, 128, PACKF * 4>>>();
    out_kernel<<<BATCH * 45 / 256, 256>>>(bf, (float*)d_out);
}

// round 4
// speedup vs baseline: 1.3320x; 1.1298x over previous
#include <cuda_runtime.h>
#include <cstdint>

typedef unsigned long long u64;
typedef unsigned int u32;

#define BATCH 65536
#define NBLK 518
#define PACKF (NBLK * 48)          // 24864 floats (duplicated f32x2 weight pack)
#define NDIFF 514
#define OUT_STAB_OFF (BATCH * 180)
#define MAIN_CTAS 128

__device__ __align__(16) float g_wpack[PACKF];
__device__ __align__(16) float g_seed[BATCH * 3];
__device__ __align__(16) float g_S3[BATCH * 3];
__device__ __align__(16) float g_M[540];
__device__ float g_rs[86];          // rowsums of R0 (2), R1 (12), R2 (72)
__device__ float g_rs3[432];        // rowsums of R3
__device__ u32 g_dpart[NDIFF * MAIN_CTAS];   // per-CTA fixed-point diff partials

// ---------------- f32x2 helpers ----------------
__device__ __forceinline__ u64 pk2(float lo, float hi) {
    u64 r; asm("mov.b64 %0, {%1, %2};" : "=l"(r) : "f"(lo), "f"(hi)); return r;
}
__device__ __forceinline__ void upk2(u64 v, float& lo, float& hi) {
    asm("mov.b64 {%0, %1}, %2;" : "=f"(lo), "=f"(hi) : "l"(v));
}
__device__ __forceinline__ u64 fma2(u64 a, u64 b, u64 c) {
    u64 d; asm("fma.rn.f32x2 %0, %1, %2, %3;" : "=l"(d) : "l"(a), "l"(b), "l"(c)); return d;
}
__device__ __forceinline__ u64 add2(u64 a, u64 b) {
    u64 d; asm("add.rn.f32x2 %0, %1, %2;" : "=l"(d) : "l"(a), "l"(b)); return d;
}
__device__ __forceinline__ u64 tanh2(u64 v) {
    float a, b;
    asm("mov.b64 {%0, %1}, %2;" : "=f"(a), "=f"(b) : "l"(v));
    asm("tanh.approx.f32 %0, %0;" : "+f"(a));
    asm("tanh.approx.f32 %0, %0;" : "+f"(b));
    u64 r;
    asm("mov.b64 %0, {%1, %2};" : "=l"(r) : "f"(a), "f"(b));
    return r;
}
__device__ __forceinline__ float habs(u64 v) {   // |lo| + |hi|
    float a, b; upk2(v, a, b); return fabsf(a) + fabsf(b);
}

// ---------------------------------------------------------------------------
// s1: 621 CTAs x 128 thr.
//   CTAs 0..511  : seed for 128 rows each (x + W_logic staged in smem, float4)
//   CTA 512      : rowsums r0,r1,r2 -> g_rs; zero g_M
//   CTAs 513..620: rowsums of R3 (warp per row, 4 rows/CTA) -> g_rs3
// ---------------------------------------------------------------------------
#define SEED_CTAS 512
#define S1_SMEM (128 * 46 * 8 + 276 * 4)   // x: 128 rows x 46 float2 ; w: 276 f

__global__ void __launch_bounds__(128) s1_kernel(
    const float* __restrict__ x,  const float* __restrict__ Wl, const float* __restrict__ Wi,
    const float* __restrict__ R0, const float* __restrict__ R1,
    const float* __restrict__ R2, const float* __restrict__ R3)
{
    extern __shared__ float2 s_x2[];
    const int tid = threadIdx.x;
    const int bid = blockIdx.x;

    if (bid < SEED_CTAS) {
        float* s_w = (float*)(s_x2 + 128 * 46);     // 276 floats (270 + zero pad)
        const int base = bid * 128;
        const float2* xg = (const float2*)(x + (size_t)base * 90);
        for (int e = tid; e < 128 * 45; e += 128) {
            int r = e / 45;
            int k = e - r * 45;
            s_x2[r * 46 + k] = xg[e];
        }
        s_x2[tid * 46 + 45] = make_float2(0.f, 0.f);   // zero pad per row
        for (int i = tid; i < 138; i += 128) {
            float2 v = make_float2(0.f, 0.f);
            if (i < 135) v = ((const float2*)Wl)[i];
            ((float2*)s_w)[i] = v;
        }
        __syncthreads();

        const float4* xr  = (const float4*)s_x2 + tid * 23;   // 92 floats = 23 f4
        const float4* w4  = (const float4*)s_w;
        float L0 = 0.f, L1 = 0.f, L2 = 0.f;
        #pragma unroll
        for (int c = 0; c < 23; c++) {
            float4 xv = xr[c];
            float4 w0 = w4[3 * c], w1 = w4[3 * c + 1], w2 = w4[3 * c + 2];
            L0 = fmaf(xv.x, w0.x, L0); L1 = fmaf(xv.x, w0.y, L1); L2 = fmaf(xv.x, w0.z, L2);
            L0 = fmaf(xv.y, w0.w, L0); L1 = fmaf(xv.y, w1.x, L1); L2 = fmaf(xv.y, w1.y, L2);
            L0 = fmaf(xv.z, w1.z, L0); L1 = fmaf(xv.z, w1.w, L1); L2 = fmaf(xv.z, w2.x, L2);
            L0 = fmaf(xv.w, w2.y, L0); L1 = fmaf(xv.w, w2.z, L1); L2 = fmaf(xv.w, w2.w, L2);
        }
        const float C = 2.0943951023931953f;   // 2*pi/3
        float E0 = __sinf(C * L0), E1 = __sinf(C * L1), E2 = __sinf(C * L2);
        float I0 = E0 * __ldg(&Wi[0]) + E1 * __ldg(&Wi[3]) + E2 * __ldg(&Wi[6]);
        float I1 = E0 * __ldg(&Wi[1]) + E1 * __ldg(&Wi[4]) + E2 * __ldg(&Wi[7]);
        float I2 = E0 * __ldg(&Wi[2]) + E1 * __ldg(&Wi[5]) + E2 * __ldg(&Wi[8]);
        const float TH = 1.0f / 3.0f;
        int row = base + tid;
        g_seed[row * 3 + 0] = (L0 + E0 + I0) * TH;
        g_seed[row * 3 + 1] = (L1 + E1 + I1) * TH;
        g_seed[row * 3 + 2] = (L2 + E2 + I2) * TH;
    } else if (bid == SEED_CTAS) {
        int wid = tid >> 5, lane = tid & 31;
        for (int rr = wid; rr < 86; rr += 4) {
            const float* Rp; int n, row;
            if (rr < 2)       { Rp = R0; n = 2;  row = rr; }
            else if (rr < 14) { Rp = R1; n = 12; row = rr - 2; }
            else              { Rp = R2; n = 72; row = rr - 14; }
            float s = 0.f;
            for (int kk = lane; kk < n; kk += 32) s += Rp[row * n + kk];
            #pragma unroll
            for (int o = 16; o; o >>= 1) s += __shfl_xor_sync(0xffffffffu, s, o);
            if (lane == 0) g_rs[rr] = s;
        }
        for (int i = tid; i < 540; i += 128) g_M[i] = 0.f;
    } else {
        int wid = tid >> 5, lane = tid & 31;
        int row = (bid - SEED_CTAS - 1) * 4 + wid;
        const float* Rp = R3 + row * 432;
        float s = 0.f;
        #pragma unroll 7
        for (int kk = lane; kk < 432; kk += 32) s += Rp[kk];
        #pragma unroll
        for (int o = 16; o; o >>= 1) s += __shfl_xor_sync(0xffffffffu, s, o);
        if (lane == 0) g_rs3[row] = s;
    }
}

// ---------------------------------------------------------------------------
// s2: 13 CTAs x 256 thr.
//   CTAs 0..8 : M partials over 48 i-indices each (coalesced Wf reads + atomics)
//   CTAs 9..12: duplicated f32x2 weight pack (c folded into W1)
// ---------------------------------------------------------------------------
__global__ void __launch_bounds__(256) s2_kernel(
    const float* __restrict__ Wf,
    const float* __restrict__ W1_0, const float* __restrict__ b1_0,
    const float* __restrict__ W2_0, const float* __restrict__ b2_0,
    const float* __restrict__ W1_1, const float* __restrict__ b1_1,
    const float* __restrict__ W2_1, const float* __restrict__ b2_1,
    const float* __restrict__ W1_2, const float* __restrict__ b1_2,
    const float* __restrict__ W2_2, const float* __restrict__ b2_2,
    const float* __restrict__ W1_3, const float* __restrict__ b1_3,
    const float* __restrict__ W2_3, const float* __restrict__ b2_3)
{
    const int tid = threadIdx.x;
    const int bid = blockIdx.x;

    if (bid < 9) {
        __shared__ float r3c[48];
        const int i0 = bid * 48;
        if (tid < 48) r3c[tid] = g_rs3[i0 + tid];
        __syncthreads();
        if (tid < 180) {
            float a0 = 0.f, a1 = 0.f, a2 = 0.f;
            const float* basep = Wf + (size_t)(3 * i0) * 180 + tid;
            #pragma unroll 4
            for (int ii = 0; ii < 48; ii++) {
                float rv = r3c[ii];
                a0 = fmaf(rv, __ldg(basep + (3 * ii + 0) * 180), a0);
                a1 = fmaf(rv, __ldg(basep + (3 * ii + 1) * 180), a1);
                a2 = fmaf(rv, __ldg(basep + (3 * ii + 2) * 180), a2);
            }
            atomicAdd(&g_M[0 * 180 + tid], a0);
            atomicAdd(&g_M[1 * 180 + tid], a1);
            atomicAdd(&g_M[2 * 180 + tid], a2);
        }
    } else {
        for (int e = (bid - 9) * 256 + tid; e < NBLK * 24; e += 4 * 256) {
            int blk = e / 24, k = e - blk * 24;
            int l, j;
            if (blk < 2)       { l = 0; j = blk; }
            else if (blk < 14) { l = 1; j = blk - 2; }
            else if (blk < 86) { l = 2; j = blk - 14; }
            else               { l = 3; j = blk - 86; }
            float c = 1.f;
            if (l == 1)      c = __ldg(&g_rs[0 + (j & 1)]);
            else if (l == 2) c = __ldg(&g_rs[2 + (j % 12)]);
            else if (l == 3) c = __ldg(&g_rs[14 + (j % 72)]);
            const float *W1p, *B1p, *W2p, *B2p;
            if (l == 0)      { W1p = W1_0; B1p = b1_0; W2p = W2_0; B2p = b2_0; }
            else if (l == 1) { W1p = W1_1; B1p = b1_1; W2p = W2_1; B2p = b2_1; }
            else if (l == 2) { W1p = W1_2; B1p = b1_2; W2p = W2_2; B2p = b2_2; }
            else             { W1p = W1_3; B1p = b1_3; W2p = W2_3; B2p = b2_3; }
            float v;
            if (k < 9)       v = c * W1p[j * 9 + k];
            else if (k < 12) v = B1p[j * 3 + (k - 9)];
            else if (k < 21) v = W2p[j * 9 + (k - 12)];
            else             v = B2p[j * 3 + (k - 21)];
            g_wpack[2 * e]     = v;
            g_wpack[2 * e + 1] = v;
        }
    }
}

// ---------------------------------------------------------------------------
// Main kernel: 128 CTAs x 256 thr, 2 batch elems/thread (1 f32x2 pair).
// 2 warps/SMSP. Diffs: warp REDUX -> own smem slot (no atomics); per-CTA
// partial sums exported via plain STG at the end.
// ---------------------------------------------------------------------------
__global__ void __launch_bounds__(256) main_kernel() {
    extern __shared__ u64 sw[];                     // weights: PACKF/2 u64
    u32* sdiff = (u32*)(sw + PACKF / 2);            // [NDIFF][8] per-warp slots
    {
        const float4* src = (const float4*)g_wpack;
        float4* dst = (float4*)sw;
        for (int i = threadIdx.x; i < PACKF / 4; i += 256) dst[i] = src[i];
    }
    __syncthreads();

    const int tid  = threadIdx.x;
    const int wid  = tid >> 5;
    const int lane = tid & 31;
    const int T = blockIdx.x * 256 + tid;           // pair index, rows 2T,2T+1
    const float2* sp = (const float2*)g_seed + 3 * T;
    float2 v0 = sp[0], v1 = sp[1], v2 = sp[2];
    u64 S0 = pk2(v0.x, v1.y), S1 = pk2(v0.y, v2.x), S2 = pk2(v1.x, v2.y);

    const u64 NEG1 = 0xBF800000BF800000ull;
    const u64* w = sw;
    int didx = 0;
    const int nbl[4] = {2, 12, 72, 432};

    #pragma unroll
    for (int l = 0; l < 4; l++) {
        u64 a0 = 0, a1 = 0, a2 = 0;
        u64 p0 = 0, p1 = 0, p2 = 0;
        const int n = nbl[l];
        #pragma unroll 2
        for (int j = 0; j < n; j++) {
            const ulonglong2* w2 = (const ulonglong2*)w;
            ulonglong2 q0 = w2[0], q1 = w2[1], q2 = w2[2], q3 = w2[3],
                       q4 = w2[4], q5 = w2[5];
            u64 h0 = fma2(S0, q0.x, fma2(S1, q1.y, fma2(S2, q3.x, q4.y)));
            u64 h1 = fma2(S0, q0.y, fma2(S1, q2.x, fma2(S2, q3.y, q5.x)));
            u64 h2 = fma2(S0, q1.x, fma2(S1, q2.y, fma2(S2, q4.x, q5.y)));
            h0 = tanh2(h0); h1 = tanh2(h1); h2 = tanh2(h2);
            ulonglong2 r0 = w2[6], r1 = w2[7], r2 = w2[8], r3 = w2[9],
                       r4 = w2[10], r5 = w2[11];
            u64 o0 = fma2(h0, r0.x, fma2(h1, r1.y, fma2(h2, r3.x, r4.y)));
            u64 o1 = fma2(h0, r0.y, fma2(h1, r2.x, fma2(h2, r3.y, r5.x)));
            u64 o2 = fma2(h0, r1.x, fma2(h1, r2.y, fma2(h2, r4.x, r5.y)));
            a0 = add2(a0, o0); a1 = add2(a1, o1); a2 = add2(a2, o2);
            if (j) {
                u64 e0 = fma2(p0, NEG1, o0), e1 = fma2(p1, NEG1, o1),
                    e2 = fma2(p2, NEG1, o2);
                float ds = (habs(e0) + habs(e1)) + habs(e2);
                u32 fx = __float2uint_rn(ds * 65536.0f);
                fx = __reduce_add_sync(0xffffffffu, fx);
                if (lane == 0) sdiff[didx * 8 + wid] = fx;
                didx++;
            }
            p0 = o0; p1 = o1; p2 = o2;
            w += 24;
        }
        S0 = a0; S1 = a1; S2 = a2;
    }

    // write S3 rows 2T, 2T+1
    float a0l, a0h, a1l, a1h, a2l, a2h;
    upk2(S0, a0l, a0h); upk2(S1, a1l, a1h); upk2(S2, a2l, a2h);
    float2* op = (float2*)g_S3 + 3 * T;
    op[0] = make_float2(a0l, a1l);
    op[1] = make_float2(a2l, a0h);
    op[2] = make_float2(a1h, a2h);

    // export per-CTA diff partials
    __syncthreads();
    for (int d = tid; d < NDIFF; d += 256) {
        u32 s = 0;
        #pragma unroll
        for (int ww = 0; ww < 8; ww++) s += sdiff[d * 8 + ww];
        g_dpart[d * MAIN_CTAS + blockIdx.x] = s;
    }
}

// ---------------------------------------------------------------------------
// stab_kernel: 65 CTAs x 256 thr; warp per didx, coalesced reduce over CTAs.
// ---------------------------------------------------------------------------
__global__ void __launch_bounds__(256) stab_kernel(float* __restrict__ out) {
    const int gw = (blockIdx.x * 256 + threadIdx.x) >> 5;
    const int lane = threadIdx.x & 31;
    if (blockIdx.x == 0 && threadIdx.x < 4) {
        const int firsts[4] = {0, 2, 14, 86};
        out[OUT_STAB_OFF + firsts[threadIdx.x]] = 1.0f;
    }
    if (gw >= NDIFF) return;
    u64 s = 0;
    #pragma unroll
    for (int k = 0; k < 4; k++) s += (u64)g_dpart[gw * MAIN_CTAS + lane + k * 32];
    #pragma unroll
    for (int o = 16; o; o >>= 1) s += __shfl_xor_sync(0xffffffffu, s, o);
    if (lane == 0) {
        int sidx = gw + ((gw >= 83) ? 4 : (gw >= 12) ? 3 : (gw >= 1) ? 2 : 1);
        double mean = (double)s * (1.0 / (65536.0 * 65536.0 * 3.0));
        double v = 1.0 - mean;
        out[OUT_STAB_OFF + sidx] = (float)(v > 0.0 ? v : 0.0);
    }
}

// ---------------------------------------------------------------------------
// Epilogue: out[b,:] = S3[b,:] @ M + b_final. M and b_final staged in smem.
// ---------------------------------------------------------------------------
__global__ void __launch_bounds__(256) out_kernel(const float* __restrict__ bfin,
                                                  float* __restrict__ out) {
    __shared__ __align__(16) float sM[720];
    for (int i = threadIdx.x; i < 720; i += 256)
        sM[i] = (i < 540) ? g_M[i] : __ldg(&bfin[i - 540]);
    __syncthreads();

    int idx = blockIdx.x * 256 + threadIdx.x;          // 0 .. 65536*45-1
    int b = idx / 45;
    int c = idx - b * 45;
    float s0 = __ldg(&g_S3[b * 3 + 0]);
    float s1 = __ldg(&g_S3[b * 3 + 1]);
    float s2 = __ldg(&g_S3[b * 3 + 2]);
    float4 m0 = *(const float4*)&sM[4 * c];
    float4 m1 = *(const float4*)&sM[180 + 4 * c];
    float4 m2 = *(const float4*)&sM[360 + 4 * c];
    float4 bf = *(const float4*)&sM[540 + 4 * c];
    float4 r;
    r.x = fmaf(s0, m0.x, fmaf(s1, m1.x, fmaf(s2, m2.x, bf.x)));
    r.y = fmaf(s0, m0.y, fmaf(s1, m1.y, fmaf(s2, m2.y, bf.y)));
    r.z = fmaf(s0, m0.z, fmaf(s1, m1.z, fmaf(s2, m2.z, bf.z)));
    r.w = fmaf(s0, m0.w, fmaf(s1, m1.w, fmaf(s2, m2.w, bf.w)));
    ((float4*)out)[idx] = r;
}

extern "C" void kernel_launch(void* const* d_in, const int* in_sizes, int n_in,
                              void* d_out, int out_size) {
    const float* x    = (const float*)d_in[0];
    const float* Wl   = (const float*)d_in[1];
    const float* Wi   = (const float*)d_in[2];
    const float* W1_0 = (const float*)d_in[3];
    const float* b1_0 = (const float*)d_in[4];
    const float* W2_0 = (const float*)d_in[5];
    const float* b2_0 = (const float*)d_in[6];
    const float* R0   = (const float*)d_in[7];
    const float* W1_1 = (const float*)d_in[8];
    const float* b1_1 = (const float*)d_in[9];
    const float* W2_1 = (const float*)d_in[10];
    const float* b2_1 = (const float*)d_in[11];
    const float* R1   = (const float*)d_in[12];
    const float* W1_2 = (const float*)d_in[13];
    const float* b1_2 = (const float*)d_in[14];
    const float* W2_2 = (const float*)d_in[15];
    const float* b2_2 = (const float*)d_in[16];
    const float* R2   = (const float*)d_in[17];
    const float* W1_3 = (const float*)d_in[18];
    const float* b1_3 = (const float*)d_in[19];
    const float* W2_3 = (const float*)d_in[20];
    const float* b2_3 = (const float*)d_in[21];
    const float* R3   = (const float*)d_in[22];
    const float* Wf   = (const float*)d_in[23];
    const float* bf   = (const float*)d_in[24];

    const int main_smem = PACKF * 4 + NDIFF * 8 * 4;
    cudaFuncSetAttribute(main_kernel, cudaFuncAttributeMaxDynamicSharedMemorySize, main_smem);

    s1_kernel<<<SEED_CTAS + 1 + 108, 128, S1_SMEM>>>(x, Wl, Wi, R0, R1, R2, R3);
    s2_kernel<<<13, 256>>>(Wf,
        W1_0, b1_0, W2_0, b2_0,
        W1_1, b1_1, W2_1, b2_1,
        W1_2, b1_2, W2_2, b2_2,
        W1_3, b1_3, W2_3, b2_3);
    main_kernel<<<MAIN_CTAS, 256, main_smem>>>();
    stab_kernel<<<65, 256>>>((float*)d_out);
    out_kernel<<<BATCH * 45 / 256, 256>>>(bf, (float*)d_out);
}

// round 5
// speedup vs baseline: 1.4119x; 1.0600x over previous
#include <cuda_runtime.h>
#include <cstdint>

typedef unsigned long long u64;
typedef unsigned int u32;

#define BATCH 65536
#define NBLK 518
#define PACKF (NBLK * 48)          // 24864 floats (duplicated f32x2 weight pack)
#define OUT_STAB_OFF (BATCH * 180)
#define MAIN_CTAS 128

__device__ __align__(16) float g_wpack[PACKF];
__device__ __align__(16) float g_seed[BATCH * 3];
__device__ __align__(16) float g_S3[BATCH * 3];
__device__ __align__(16) float g_M[540];
__device__ float g_rs[86];          // rowsums of R0 (2), R1 (12), R2 (72)
__device__ float g_rs3[432];        // rowsums of R3
__device__ u32 g_dpart[NBLK * MAIN_CTAS];   // per-CTA fixed-point diff partials

// ---------------- f32x2 helpers ----------------
__device__ __forceinline__ u64 pk2(float lo, float hi) {
    u64 r; asm("mov.b64 %0, {%1, %2};" : "=l"(r) : "f"(lo), "f"(hi)); return r;
}
__device__ __forceinline__ void upk2(u64 v, float& lo, float& hi) {
    asm("mov.b64 {%0, %1}, %2;" : "=f"(lo), "=f"(hi) : "l"(v));
}
__device__ __forceinline__ u64 fma2(u64 a, u64 b, u64 c) {
    u64 d; asm("fma.rn.f32x2 %0, %1, %2, %3;" : "=l"(d) : "l"(a), "l"(b), "l"(c)); return d;
}
__device__ __forceinline__ u64 add2(u64 a, u64 b) {
    u64 d; asm("add.rn.f32x2 %0, %1, %2;" : "=l"(d) : "l"(a), "l"(b)); return d;
}
__device__ __forceinline__ u64 tanh2(u64 v) {
    float a, b;
    asm("mov.b64 {%0, %1}, %2;" : "=f"(a), "=f"(b) : "l"(v));
    asm("tanh.approx.f32 %0, %0;" : "+f"(a));
    asm("tanh.approx.f32 %0, %0;" : "+f"(b));
    u64 r;
    asm("mov.b64 %0, {%1, %2};" : "=l"(r) : "f"(a), "f"(b));
    return r;
}
__device__ __forceinline__ float habs(u64 v) {   // |lo| + |hi|
    float a, b; upk2(v, a, b); return fabsf(a) + fabsf(b);
}

// ---------------------------------------------------------------------------
// s1: 621 CTAs x 128 thr.
//   CTAs 0..511  : seed for 128 rows each (x + W_logic staged in smem, float4)
//   CTA 512      : rowsums r0,r1,r2 -> g_rs; zero g_M
//   CTAs 513..620: rowsums of R3 (warp per row, 4 rows/CTA) -> g_rs3
// ---------------------------------------------------------------------------
#define SEED_CTAS 512
#define S1_SMEM (128 * 46 * 8 + 276 * 4)   // x: 128 rows x 46 float2 ; w: 276 f

__global__ void __launch_bounds__(128) s1_kernel(
    const float* __restrict__ x,  const float* __restrict__ Wl, const float* __restrict__ Wi,
    const float* __restrict__ R0, const float* __restrict__ R1,
    const float* __restrict__ R2, const float* __restrict__ R3)
{
    extern __shared__ float2 s_x2[];
    const int tid = threadIdx.x;
    const int bid = blockIdx.x;

    if (bid < SEED_CTAS) {
        float* s_w = (float*)(s_x2 + 128 * 46);     // 276 floats (270 + zero pad)
        const int base = bid * 128;
        const float2* xg = (const float2*)(x + (size_t)base * 90);
        for (int e = tid; e < 128 * 45; e += 128) {
            int r = e / 45;
            int k = e - r * 45;
            s_x2[r * 46 + k] = xg[e];
        }
        s_x2[tid * 46 + 45] = make_float2(0.f, 0.f);   // zero pad per row
        for (int i = tid; i < 138; i += 128) {
            float2 v = make_float2(0.f, 0.f);
            if (i < 135) v = ((const float2*)Wl)[i];
            ((float2*)s_w)[i] = v;
        }
        __syncthreads();

        const float4* xr  = (const float4*)s_x2 + tid * 23;   // 92 floats = 23 f4
        const float4* w4  = (const float4*)s_w;
        float L0 = 0.f, L1 = 0.f, L2 = 0.f;
        #pragma unroll
        for (int c = 0; c < 23; c++) {
            float4 xv = xr[c];
            float4 w0 = w4[3 * c], w1 = w4[3 * c + 1], w2 = w4[3 * c + 2];
            L0 = fmaf(xv.x, w0.x, L0); L1 = fmaf(xv.x, w0.y, L1); L2 = fmaf(xv.x, w0.z, L2);
            L0 = fmaf(xv.y, w0.w, L0); L1 = fmaf(xv.y, w1.x, L1); L2 = fmaf(xv.y, w1.y, L2);
            L0 = fmaf(xv.z, w1.z, L0); L1 = fmaf(xv.z, w1.w, L1); L2 = fmaf(xv.z, w2.x, L2);
            L0 = fmaf(xv.w, w2.y, L0); L1 = fmaf(xv.w, w2.z, L1); L2 = fmaf(xv.w, w2.w, L2);
        }
        const float C = 2.0943951023931953f;   // 2*pi/3
        float E0 = __sinf(C * L0), E1 = __sinf(C * L1), E2 = __sinf(C * L2);
        float I0 = E0 * __ldg(&Wi[0]) + E1 * __ldg(&Wi[3]) + E2 * __ldg(&Wi[6]);
        float I1 = E0 * __ldg(&Wi[1]) + E1 * __ldg(&Wi[4]) + E2 * __ldg(&Wi[7]);
        float I2 = E0 * __ldg(&Wi[2]) + E1 * __ldg(&Wi[5]) + E2 * __ldg(&Wi[8]);
        const float TH = 1.0f / 3.0f;
        int row = base + tid;
        g_seed[row * 3 + 0] = (L0 + E0 + I0) * TH;
        g_seed[row * 3 + 1] = (L1 + E1 + I1) * TH;
        g_seed[row * 3 + 2] = (L2 + E2 + I2) * TH;
    } else if (bid == SEED_CTAS) {
        int wid = tid >> 5, lane = tid & 31;
        for (int rr = wid; rr < 86; rr += 4) {
            const float* Rp; int n, row;
            if (rr < 2)       { Rp = R0; n = 2;  row = rr; }
            else if (rr < 14) { Rp = R1; n = 12; row = rr - 2; }
            else              { Rp = R2; n = 72; row = rr - 14; }
            float s = 0.f;
            for (int kk = lane; kk < n; kk += 32) s += Rp[row * n + kk];
            #pragma unroll
            for (int o = 16; o; o >>= 1) s += __shfl_xor_sync(0xffffffffu, s, o);
            if (lane == 0) g_rs[rr] = s;
        }
        for (int i = tid; i < 540; i += 128) g_M[i] = 0.f;
    } else {
        int wid = tid >> 5, lane = tid & 31;
        int row = (bid - SEED_CTAS - 1) * 4 + wid;
        const float* Rp = R3 + row * 432;
        float s = 0.f;
        #pragma unroll 7
        for (int kk = lane; kk < 432; kk += 32) s += Rp[kk];
        #pragma unroll
        for (int o = 16; o; o >>= 1) s += __shfl_xor_sync(0xffffffffu, s, o);
        if (lane == 0) g_rs3[row] = s;
    }
}

// ---------------------------------------------------------------------------
// s2: 13 CTAs x 256 thr.
//   CTAs 0..8 : M partials over 48 i-indices each (coalesced Wf reads + atomics)
//   CTAs 9..12: duplicated f32x2 weight pack (c folded into W1)
// ---------------------------------------------------------------------------
__global__ void __launch_bounds__(256) s2_kernel(
    const float* __restrict__ Wf,
    const float* __restrict__ W1_0, const float* __restrict__ b1_0,
    const float* __restrict__ W2_0, const float* __restrict__ b2_0,
    const float* __restrict__ W1_1, const float* __restrict__ b1_1,
    const float* __restrict__ W2_1, const float* __restrict__ b2_1,
    const float* __restrict__ W1_2, const float* __restrict__ b1_2,
    const float* __restrict__ W2_2, const float* __restrict__ b2_2,
    const float* __restrict__ W1_3, const float* __restrict__ b1_3,
    const float* __restrict__ W2_3, const float* __restrict__ b2_3)
{
    const int tid = threadIdx.x;
    const int bid = blockIdx.x;

    if (bid < 9) {
        __shared__ float r3c[48];
        const int i0 = bid * 48;
        if (tid < 48) r3c[tid] = g_rs3[i0 + tid];
        __syncthreads();
        if (tid < 180) {
            float a0 = 0.f, a1 = 0.f, a2 = 0.f;
            const float* basep = Wf + (size_t)(3 * i0) * 180 + tid;
            #pragma unroll 4
            for (int ii = 0; ii < 48; ii++) {
                float rv = r3c[ii];
                a0 = fmaf(rv, __ldg(basep + (3 * ii + 0) * 180), a0);
                a1 = fmaf(rv, __ldg(basep + (3 * ii + 1) * 180), a1);
                a2 = fmaf(rv, __ldg(basep + (3 * ii + 2) * 180), a2);
            }
            atomicAdd(&g_M[0 * 180 + tid], a0);
            atomicAdd(&g_M[1 * 180 + tid], a1);
            atomicAdd(&g_M[2 * 180 + tid], a2);
        }
    } else {
        for (int e = (bid - 9) * 256 + tid; e < NBLK * 24; e += 4 * 256) {
            int blk = e / 24, k = e - blk * 24;
            int l, j;
            if (blk < 2)       { l = 0; j = blk; }
            else if (blk < 14) { l = 1; j = blk - 2; }
            else if (blk < 86) { l = 2; j = blk - 14; }
            else               { l = 3; j = blk - 86; }
            float c = 1.f;
            if (l == 1)      c = __ldg(&g_rs[0 + (j & 1)]);
            else if (l == 2) c = __ldg(&g_rs[2 + (j % 12)]);
            else if (l == 3) c = __ldg(&g_rs[14 + (j % 72)]);
            const float *W1p, *B1p, *W2p, *B2p;
            if (l == 0)      { W1p = W1_0; B1p = b1_0; W2p = W2_0; B2p = b2_0; }
            else if (l == 1) { W1p = W1_1; B1p = b1_1; W2p = W2_1; B2p = b2_1; }
            else if (l == 2) { W1p = W1_2; B1p = b1_2; W2p = W2_2; B2p = b2_2; }
            else             { W1p = W1_3; B1p = b1_3; W2p = W2_3; B2p = b2_3; }
            float v;
            if (k < 9)       v = c * W1p[j * 9 + k];
            else if (k < 12) v = B1p[j * 3 + (k - 9)];
            else if (k < 21) v = W2p[j * 9 + (k - 12)];
            else             v = B2p[j * 3 + (k - 21)];
            g_wpack[2 * e]     = v;
            g_wpack[2 * e + 1] = v;
        }
    }
}

// ---------------------------------------------------------------------------
// Main kernel: 128 CTAs x 256 thr, 2 batch elems/thread (1 f32x2 pair).
// Branch-free diff path: EVERY block iteration computes a diff and stores it
// to slot [blk][wid]; the first block of each layer is a dummy slot (p=0)
// that the stab reduction never reads. No BSSY/BSYNC in the hot loop.
// ---------------------------------------------------------------------------
__global__ void __launch_bounds__(256) main_kernel() {
    extern __shared__ u64 sw[];                     // weights: PACKF/2 u64
    u32* sdiff = (u32*)(sw + PACKF / 2);            // [NBLK][8] per-warp slots
    {
        const float4* src = (const float4*)g_wpack;
        float4* dst = (float4*)sw;
        for (int i = threadIdx.x; i < PACKF / 4; i += 256) dst[i] = src[i];
    }
    __syncthreads();

    const int tid  = threadIdx.x;
    const int wid  = tid >> 5;
    const int lane = tid & 31;
    const int T = blockIdx.x * 256 + tid;           // pair index, rows 2T,2T+1
    const float2* sp = (const float2*)g_seed + 3 * T;
    float2 v0 = sp[0], v1 = sp[1], v2 = sp[2];
    u64 S0 = pk2(v0.x, v1.y), S1 = pk2(v0.y, v2.x), S2 = pk2(v1.x, v2.y);

    const u64 NEG1 = 0xBF800000BF800000ull;
    const u64* w = sw;
    u32* sdp = sdiff + wid;
    const bool l0 = (lane == 0);
    const int nbl[4] = {2, 12, 72, 432};

    #pragma unroll
    for (int l = 0; l < 4; l++) {
        u64 a0 = 0, a1 = 0, a2 = 0;
        u64 p0 = 0, p1 = 0, p2 = 0;
        const int n = nbl[l];
        #pragma unroll 2
        for (int j = 0; j < n; j++) {
            const ulonglong2* w2 = (const ulonglong2*)w;
            ulonglong2 q0 = w2[0], q1 = w2[1], q2 = w2[2], q3 = w2[3],
                       q4 = w2[4], q5 = w2[5];
            u64 h0 = fma2(S0, q0.x, fma2(S1, q1.y, fma2(S2, q3.x, q4.y)));
            u64 h1 = fma2(S0, q0.y, fma2(S1, q2.x, fma2(S2, q3.y, q5.x)));
            u64 h2 = fma2(S0, q1.x, fma2(S1, q2.y, fma2(S2, q4.x, q5.y)));
            h0 = tanh2(h0); h1 = tanh2(h1); h2 = tanh2(h2);
            ulonglong2 r0 = w2[6], r1 = w2[7], r2 = w2[8], r3 = w2[9],
                       r4 = w2[10], r5 = w2[11];
            u64 o0 = fma2(h0, r0.x, fma2(h1, r1.y, fma2(h2, r3.x, r4.y)));
            u64 o1 = fma2(h0, r0.y, fma2(h1, r2.x, fma2(h2, r3.y, r5.x)));
            u64 o2 = fma2(h0, r1.x, fma2(h1, r2.y, fma2(h2, r4.x, r5.y)));
            a0 = add2(a0, o0); a1 = add2(a1, o1); a2 = add2(a2, o2);
            // branch-free diff (j==0 writes a dummy slot never read by stab)
            u64 e0 = fma2(p0, NEG1, o0), e1 = fma2(p1, NEG1, o1),
                e2 = fma2(p2, NEG1, o2);
            float ds = (habs(e0) + habs(e1)) + habs(e2);
            u32 fx = __float2uint_rn(ds * 65536.0f);
            fx = __reduce_add_sync(0xffffffffu, fx);
            if (l0) *sdp = fx;
            sdp += 8;
            p0 = o0; p1 = o1; p2 = o2;
            w += 24;
        }
        S0 = a0; S1 = a1; S2 = a2;
    }

    // write S3 rows 2T, 2T+1
    float a0l, a0h, a1l, a1h, a2l, a2h;
    upk2(S0, a0l, a0h); upk2(S1, a1l, a1h); upk2(S2, a2l, a2h);
    float2* op = (float2*)g_S3 + 3 * T;
    op[0] = make_float2(a0l, a1l);
    op[1] = make_float2(a2l, a0h);
    op[2] = make_float2(a1h, a2h);

    // export per-CTA diff partials (one u32 per block slot)
    __syncthreads();
    for (int d = tid; d < NBLK; d += 256) {
        u32 s = 0;
        #pragma unroll
        for (int ww = 0; ww < 8; ww++) s += sdiff[d * 8 + ww];
        g_dpart[d * MAIN_CTAS + blockIdx.x] = s;
    }
}

// ---------------------------------------------------------------------------
// Epilogue: out[b,:] = S3[b,:] @ M + b_final. M and b_final staged in smem.
// Warps gw<518 of the first 65 CTAs additionally produce the stab outputs.
// ---------------------------------------------------------------------------
__global__ void __launch_bounds__(256) out_kernel(const float* __restrict__ bfin,
                                                  float* __restrict__ out) {
    __shared__ __align__(16) float sM[720];
    for (int i = threadIdx.x; i < 720; i += 256)
        sM[i] = (i < 540) ? g_M[i] : __ldg(&bfin[i - 540]);

    // ---- stability outputs (first 65 CTAs, warp per block slot) ----
    const int gw = blockIdx.x * 8 + (threadIdx.x >> 5);
    if (gw < NBLK) {
        const int lane = threadIdx.x & 31;
        bool first = (gw == 0) | (gw == 2) | (gw == 14) | (gw == 86);
        u64 s = 0;
        #pragma unroll
        for (int k = 0; k < 4; k++)
            s += (u64)__ldg(&g_dpart[gw * MAIN_CTAS + lane + k * 32]);
        #pragma unroll
        for (int o = 16; o; o >>= 1) s += __shfl_xor_sync(0xffffffffu, s, o);
        if (lane == 0) {
            float val = 1.0f;
            if (!first) {
                double mean = (double)s * (1.0 / (65536.0 * 65536.0 * 3.0));
                double v = 1.0 - mean;
                val = (float)(v > 0.0 ? v : 0.0);
            }
            out[OUT_STAB_OFF + gw] = val;
        }
    }
    __syncthreads();

    int idx = blockIdx.x * 256 + threadIdx.x;          // 0 .. 65536*45-1
    int b = idx / 45;
    int c = idx - b * 45;
    float s0 = __ldg(&g_S3[b * 3 + 0]);
    float s1 = __ldg(&g_S3[b * 3 + 1]);
    float s2 = __ldg(&g_S3[b * 3 + 2]);
    float4 m0 = *(const float4*)&sM[4 * c];
    float4 m1 = *(const float4*)&sM[180 + 4 * c];
    float4 m2 = *(const float4*)&sM[360 + 4 * c];
    float4 bf = *(const float4*)&sM[540 + 4 * c];
    float4 r;
    r.x = fmaf(s0, m0.x, fmaf(s1, m1.x, fmaf(s2, m2.x, bf.x)));
    r.y = fmaf(s0, m0.y, fmaf(s1, m1.y, fmaf(s2, m2.y, bf.y)));
    r.z = fmaf(s0, m0.z, fmaf(s1, m1.z, fmaf(s2, m2.z, bf.z)));
    r.w = fmaf(s0, m0.w, fmaf(s1, m1.w, fmaf(s2, m2.w, bf.w)));
    ((float4*)out)[idx] = r;
}

extern "C" void kernel_launch(void* const* d_in, const int* in_sizes, int n_in,
                              void* d_out, int out_size) {
    const float* x    = (const float*)d_in[0];
    const float* Wl   = (const float*)d_in[1];
    const float* Wi   = (const float*)d_in[2];
    const float* W1_0 = (const float*)d_in[3];
    const float* b1_0 = (const float*)d_in[4];
    const float* W2_0 = (const float*)d_in[5];
    const float* b2_0 = (const float*)d_in[6];
    const float* R0   = (const float*)d_in[7];
    const float* W1_1 = (const float*)d_in[8];
    const float* b1_1 = (const float*)d_in[9];
    const float* W2_1 = (const float*)d_in[10];
    const float* b2_1 = (const float*)d_in[11];
    const float* R1   = (const float*)d_in[12];
    const float* W1_2 = (const float*)d_in[13];
    const float* b1_2 = (const float*)d_in[14];
    const float* W2_2 = (const float*)d_in[15];
    const float* b2_2 = (const float*)d_in[16];
    const float* R2   = (const float*)d_in[17];
    const float* W1_3 = (const float*)d_in[18];
    const float* b1_3 = (const float*)d_in[19];
    const float* W2_3 = (const float*)d_in[20];
    const float* b2_3 = (const float*)d_in[21];
    const float* R3   = (const float*)d_in[22];
    const float* Wf   = (const float*)d_in[23];
    const float* bf   = (const float*)d_in[24];

    const int main_smem = PACKF * 4 + NBLK * 8 * 4;
    cudaFuncSetAttribute(main_kernel, cudaFuncAttributeMaxDynamicSharedMemorySize, main_smem);

    s1_kernel<<<SEED_CTAS + 1 + 108, 128, S1_SMEM>>>(x, Wl, Wi, R0, R1, R2, R3);
    s2_kernel<<<13, 256>>>(Wf,
        W1_0, b1_0, W2_0, b2_0,
        W1_1, b1_1, W2_1, b2_1,
        W1_2, b1_2, W2_2, b2_2,
        W1_3, b1_3, W2_3, b2_3);
    main_kernel<<<MAIN_CTAS, 256, main_smem>>>();
    out_kernel<<<BATCH * 45 / 256, 256>>>(bf, (float*)d_out);
}

// round 6
// speedup vs baseline: 1.6158x; 1.1444x over previous
#include <cuda_runtime.h>
#include <cstdint>

typedef unsigned long long u64;
typedef unsigned int u32;

#define BATCH 65536
#define NBLK 518
#define PACKF (NBLK * 48)          // 24864 floats (duplicated f32x2 weight pack)
#define OUT_STAB_OFF (BATCH * 180)
#define MAIN_CTAS 128

__device__ __align__(16) float g_wpack[PACKF];
__device__ __align__(16) float g_seed[BATCH * 3];
__device__ __align__(16) float g_S3[BATCH * 3];
__device__ __align__(16) float g_M[540];
__device__ float g_rs[86];          // rowsums of R0 (2), R1 (12), R2 (72)
__device__ float g_rs3[432];        // rowsums of R3
__device__ u32 g_dpart[NBLK * MAIN_CTAS];   // per-CTA fixed-point diff partials

// ---------------- f32x2 helpers ----------------
__device__ __forceinline__ u64 pk2(float lo, float hi) {
    u64 r; asm("mov.b64 %0, {%1, %2};" : "=l"(r) : "f"(lo), "f"(hi)); return r;
}
__device__ __forceinline__ void upk2(u64 v, float& lo, float& hi) {
    asm("mov.b64 {%0, %1}, %2;" : "=f"(lo), "=f"(hi) : "l"(v));
}
__device__ __forceinline__ u64 fma2(u64 a, u64 b, u64 c) {
    u64 d; asm("fma.rn.f32x2 %0, %1, %2, %3;" : "=l"(d) : "l"(a), "l"(b), "l"(c)); return d;
}
__device__ __forceinline__ u64 add2(u64 a, u64 b) {
    u64 d; asm("add.rn.f32x2 %0, %1, %2;" : "=l"(d) : "l"(a), "l"(b)); return d;
}
__device__ __forceinline__ u64 abs2(u64 a) { return a & 0x7FFFFFFF7FFFFFFFull; }
__device__ __forceinline__ u64 tanh2(u64 v) {
    float a, b;
    asm("mov.b64 {%0, %1}, %2;" : "=f"(a), "=f"(b) : "l"(v));
    asm("tanh.approx.f32 %0, %0;" : "+f"(a));
    asm("tanh.approx.f32 %0, %0;" : "+f"(b));
    u64 r;
    asm("mov.b64 %0, {%1, %2};" : "=l"(r) : "f"(a), "f"(b));
    return r;
}
__device__ __forceinline__ float habs(u64 v) {   // |lo| + |hi|
    float a, b; upk2(v, a, b); return fabsf(a) + fabsf(b);
}

// ---------------------------------------------------------------------------
// s1: 621 CTAs x 128 thr (seed / small rowsums / R3 rowsums) — unchanged
// ---------------------------------------------------------------------------
#define SEED_CTAS 512
#define S1_SMEM (128 * 46 * 8 + 276 * 4)

__global__ void __launch_bounds__(128) s1_kernel(
    const float* __restrict__ x,  const float* __restrict__ Wl, const float* __restrict__ Wi,
    const float* __restrict__ R0, const float* __restrict__ R1,
    const float* __restrict__ R2, const float* __restrict__ R3)
{
    extern __shared__ float2 s_x2[];
    const int tid = threadIdx.x;
    const int bid = blockIdx.x;

    if (bid < SEED_CTAS) {
        float* s_w = (float*)(s_x2 + 128 * 46);
        const int base = bid * 128;
        const float2* xg = (const float2*)(x + (size_t)base * 90);
        for (int e = tid; e < 128 * 45; e += 128) {
            int r = e / 45;
            int k = e - r * 45;
            s_x2[r * 46 + k] = xg[e];
        }
        s_x2[tid * 46 + 45] = make_float2(0.f, 0.f);
        for (int i = tid; i < 138; i += 128) {
            float2 v = make_float2(0.f, 0.f);
            if (i < 135) v = ((const float2*)Wl)[i];
            ((float2*)s_w)[i] = v;
        }
        __syncthreads();

        const float4* xr  = (const float4*)s_x2 + tid * 23;
        const float4* w4  = (const float4*)s_w;
        float L0 = 0.f, L1 = 0.f, L2 = 0.f;
        #pragma unroll
        for (int c = 0; c < 23; c++) {
            float4 xv = xr[c];
            float4 w0 = w4[3 * c], w1 = w4[3 * c + 1], w2 = w4[3 * c + 2];
            L0 = fmaf(xv.x, w0.x, L0); L1 = fmaf(xv.x, w0.y, L1); L2 = fmaf(xv.x, w0.z, L2);
            L0 = fmaf(xv.y, w0.w, L0); L1 = fmaf(xv.y, w1.x, L1); L2 = fmaf(xv.y, w1.y, L2);
            L0 = fmaf(xv.z, w1.z, L0); L1 = fmaf(xv.z, w1.w, L1); L2 = fmaf(xv.z, w2.x, L2);
            L0 = fmaf(xv.w, w2.y, L0); L1 = fmaf(xv.w, w2.z, L1); L2 = fmaf(xv.w, w2.w, L2);
        }
        const float C = 2.0943951023931953f;
        float E0 = __sinf(C * L0), E1 = __sinf(C * L1), E2 = __sinf(C * L2);
        float I0 = E0 * __ldg(&Wi[0]) + E1 * __ldg(&Wi[3]) + E2 * __ldg(&Wi[6]);
        float I1 = E0 * __ldg(&Wi[1]) + E1 * __ldg(&Wi[4]) + E2 * __ldg(&Wi[7]);
        float I2 = E0 * __ldg(&Wi[2]) + E1 * __ldg(&Wi[5]) + E2 * __ldg(&Wi[8]);
        const float TH = 1.0f / 3.0f;
        int row = base + tid;
        g_seed[row * 3 + 0] = (L0 + E0 + I0) * TH;
        g_seed[row * 3 + 1] = (L1 + E1 + I1) * TH;
        g_seed[row * 3 + 2] = (L2 + E2 + I2) * TH;
    } else if (bid == SEED_CTAS) {
        int wid = tid >> 5, lane = tid & 31;
        for (int rr = wid; rr < 86; rr += 4) {
            const float* Rp; int n, row;
            if (rr < 2)       { Rp = R0; n = 2;  row = rr; }
            else if (rr < 14) { Rp = R1; n = 12; row = rr - 2; }
            else              { Rp = R2; n = 72; row = rr - 14; }
            float s = 0.f;
            for (int kk = lane; kk < n; kk += 32) s += Rp[row * n + kk];
            #pragma unroll
            for (int o = 16; o; o >>= 1) s += __shfl_xor_sync(0xffffffffu, s, o);
            if (lane == 0) g_rs[rr] = s;
        }
        for (int i = tid; i < 540; i += 128) g_M[i] = 0.f;
    } else {
        int wid = tid >> 5, lane = tid & 31;
        int row = (bid - SEED_CTAS - 1) * 4 + wid;
        const float* Rp = R3 + row * 432;
        float s = 0.f;
        #pragma unroll 7
        for (int kk = lane; kk < 432; kk += 32) s += Rp[kk];
        #pragma unroll
        for (int o = 16; o; o >>= 1) s += __shfl_xor_sync(0xffffffffu, s, o);
        if (lane == 0) g_rs3[row] = s;
    }
}

// ---------------------------------------------------------------------------
// s2: 13 CTAs x 256 thr (M partials + weight pack) — unchanged
// ---------------------------------------------------------------------------
__global__ void __launch_bounds__(256) s2_kernel(
    const float* __restrict__ Wf,
    const float* __restrict__ W1_0, const float* __restrict__ b1_0,
    const float* __restrict__ W2_0, const float* __restrict__ b2_0,
    const float* __restrict__ W1_1, const float* __restrict__ b1_1,
    const float* __restrict__ W2_1, const float* __restrict__ b2_1,
    const float* __restrict__ W1_2, const float* __restrict__ b1_2,
    const float* __restrict__ W2_2, const float* __restrict__ b2_2,
    const float* __restrict__ W1_3, const float* __restrict__ b1_3,
    const float* __restrict__ W2_3, const float* __restrict__ b2_3)
{
    const int tid = threadIdx.x;
    const int bid = blockIdx.x;

    if (bid < 9) {
        __shared__ float r3c[48];
        const int i0 = bid * 48;
        if (tid < 48) r3c[tid] = g_rs3[i0 + tid];
        __syncthreads();
        if (tid < 180) {
            float a0 = 0.f, a1 = 0.f, a2 = 0.f;
            const float* basep = Wf + (size_t)(3 * i0) * 180 + tid;
            #pragma unroll 4
            for (int ii = 0; ii < 48; ii++) {
                float rv = r3c[ii];
                a0 = fmaf(rv, __ldg(basep + (3 * ii + 0) * 180), a0);
                a1 = fmaf(rv, __ldg(basep + (3 * ii + 1) * 180), a1);
                a2 = fmaf(rv, __ldg(basep + (3 * ii + 2) * 180), a2);
            }
            atomicAdd(&g_M[0 * 180 + tid], a0);
            atomicAdd(&g_M[1 * 180 + tid], a1);
            atomicAdd(&g_M[2 * 180 + tid], a2);
        }
    } else {
        for (int e = (bid - 9) * 256 + tid; e < NBLK * 24; e += 4 * 256) {
            int blk = e / 24, k = e - blk * 24;
            int l, j;
            if (blk < 2)       { l = 0; j = blk; }
            else if (blk < 14) { l = 1; j = blk - 2; }
            else if (blk < 86) { l = 2; j = blk - 14; }
            else               { l = 3; j = blk - 86; }
            float c = 1.f;
            if (l == 1)      c = __ldg(&g_rs[0 + (j & 1)]);
            else if (l == 2) c = __ldg(&g_rs[2 + (j % 12)]);
            else if (l == 3) c = __ldg(&g_rs[14 + (j % 72)]);
            const float *W1p, *B1p, *W2p, *B2p;
            if (l == 0)      { W1p = W1_0; B1p = b1_0; W2p = W2_0; B2p = b2_0; }
            else if (l == 1) { W1p = W1_1; B1p = b1_1; W2p = W2_1; B2p = b2_1; }
            else if (l == 2) { W1p = W1_2; B1p = b1_2; W2p = W2_2; B2p = b2_2; }
            else             { W1p = W1_3; B1p = b1_3; W2p = W2_3; B2p = b2_3; }
            float v;
            if (k < 9)       v = c * W1p[j * 9 + k];
            else if (k < 12) v = B1p[j * 3 + (k - 9)];
            else if (k < 21) v = W2p[j * 9 + (k - 12)];
            else             v = B2p[j * 3 + (k - 21)];
            g_wpack[2 * e]     = v;
            g_wpack[2 * e + 1] = v;
        }
    }
}

// ---------------------------------------------------------------------------
// Main kernel: 128 CTAs x 256 thr. Block-split warp specialization:
// warps 0-3 process blocks [0, n/2), warps 4-7 blocks [n/2, n) of each layer
// for the SAME 4 batch elems/thread (2 f32x2 pairs). Partial S exchanged via
// smem at the 4 layer boundaries; boundary-block diff computed by the high
// half after the sync. First iteration of each half peeled (no diff select).
// ---------------------------------------------------------------------------
#define XCH_PER_LAYER 2304   // u64: a_low 768 | a_high 768 | p_low 768
#define MAIN_SMEM (PACKF * 4 + NBLK * 8 * 4 + 4 * XCH_PER_LAYER * 8)

#define BLK(W)                                                              \
    do {                                                                    \
        ulonglong2 q0=(W)[0],q1=(W)[1],q2=(W)[2],q3=(W)[3],q4=(W)[4],q5=(W)[5]; \
        u64 hA0=fma2(SA0,q0.x,fma2(SA1,q1.y,fma2(SA2,q3.x,q4.y)));          \
        u64 hA1=fma2(SA0,q0.y,fma2(SA1,q2.x,fma2(SA2,q3.y,q5.x)));          \
        u64 hA2=fma2(SA0,q1.x,fma2(SA1,q2.y,fma2(SA2,q4.x,q5.y)));          \
        u64 hB0=fma2(SB0,q0.x,fma2(SB1,q1.y,fma2(SB2,q3.x,q4.y)));          \
        u64 hB1=fma2(SB0,q0.y,fma2(SB1,q2.x,fma2(SB2,q3.y,q5.x)));          \
        u64 hB2=fma2(SB0,q1.x,fma2(SB1,q2.y,fma2(SB2,q4.x,q5.y)));          \
        hA0=tanh2(hA0); hA1=tanh2(hA1); hA2=tanh2(hA2);                     \
        hB0=tanh2(hB0); hB1=tanh2(hB1); hB2=tanh2(hB2);                     \
        ulonglong2 r0=(W)[6],r1=(W)[7],r2=(W)[8],r3=(W)[9],r4=(W)[10],r5=(W)[11]; \
        oA0=fma2(hA0,r0.x,fma2(hA1,r1.y,fma2(hA2,r3.x,r4.y)));              \
        oA1=fma2(hA0,r0.y,fma2(hA1,r2.x,fma2(hA2,r3.y,r5.x)));              \
        oA2=fma2(hA0,r1.x,fma2(hA1,r2.y,fma2(hA2,r4.x,r5.y)));              \
        oB0=fma2(hB0,r0.x,fma2(hB1,r1.y,fma2(hB2,r3.x,r4.y)));              \
        oB1=fma2(hB0,r0.y,fma2(hB1,r2.x,fma2(hB2,r3.y,r5.x)));              \
        oB2=fma2(hB0,r1.x,fma2(hB1,r2.y,fma2(hB2,r4.x,r5.y)));              \
    } while (0)

__global__ void __launch_bounds__(256) main_kernel() {
    extern __shared__ u64 sw[];                      // weights: PACKF/2 u64
    u32* sdiff = (u32*)(sw + PACKF / 2);             // [NBLK][8]
    u64* xch = (u64*)(sdiff + NBLK * 8);             // 4 * XCH_PER_LAYER u64
    {
        const float4* src = (const float4*)g_wpack;
        float4* dst = (float4*)sw;
        for (int i = threadIdx.x; i < PACKF / 4; i += 256) dst[i] = src[i];
        for (int i = threadIdx.x; i < NBLK * 8; i += 256) sdiff[i] = 0u;
    }
    __syncthreads();

    const int tid  = threadIdx.x;
    const int wid  = tid >> 5;
    const int lane = tid & 31;
    const bool high = (wid >= 4);
    const bool l0   = (lane == 0);
    const int i = tid & 127;                         // pair-group within CTA
    const int g = blockIdx.x * 128 + i;              // rows 4g..4g+3

    const float4* sp = (const float4*)g_seed + 3 * g;
    float4 v0 = sp[0], v1 = sp[1], v2 = sp[2];
    u64 SA0 = pk2(v0.x, v0.w), SA1 = pk2(v0.y, v1.x), SA2 = pk2(v0.z, v1.y);
    u64 SB0 = pk2(v1.z, v2.y), SB1 = pk2(v1.w, v2.z), SB2 = pk2(v2.x, v2.w);

    const u64 NEG1 = 0xBF800000BF800000ull;
    const u64* wl = sw;
    int blkbase = 0;
    const int nbl[4] = {2, 12, 72, 432};

    #pragma unroll
    for (int l = 0; l < 4; l++) {
        const int n = nbl[l];
        const int half = n >> 1;
        const ulonglong2* w2 = (const ulonglong2*)(wl + (high ? half * 24 : 0));

        u64 oA0, oA1, oA2, oB0, oB1, oB2;
        BLK(w2);                                     // peeled first block
        u64 aA0 = oA0, aA1 = oA1, aA2 = oA2, aB0 = oB0, aB1 = oB1, aB2 = oB2;
        u64 pA0 = oA0, pA1 = oA1, pA2 = oA2, pB0 = oB0, pB1 = oB1, pB2 = oB2;
        u64 fA0 = oA0, fA1 = oA1, fA2 = oA2, fB0 = oB0, fB1 = oB1, fB2 = oB2;
        w2 += 12;

        u32* sdp = sdiff + (blkbase + (high ? half : 0) + 1) * 8 + wid;
        #pragma unroll 2
        for (int j = 1; j < half; j++) {
            BLK(w2);
            aA0 = add2(aA0, oA0); aA1 = add2(aA1, oA1); aA2 = add2(aA2, oA2);
            aB0 = add2(aB0, oB0); aB1 = add2(aB1, oB1); aB2 = add2(aB2, oB2);
            u64 e0 = fma2(pA0, NEG1, oA0), e1 = fma2(pA1, NEG1, oA1),
                e2 = fma2(pA2, NEG1, oA2), e3 = fma2(pB0, NEG1, oB0),
                e4 = fma2(pB1, NEG1, oB1), e5 = fma2(pB2, NEG1, oB2);
            u64 t0 = add2(abs2(e0), abs2(e3));
            u64 t1 = add2(abs2(e1), abs2(e4));
            u64 t2 = add2(abs2(e2), abs2(e5));
            u64 tt = add2(add2(t0, t1), t2);
            u32 fx = __float2uint_rn(habs(tt) * 65536.0f);
            fx = __reduce_add_sync(0xffffffffu, fx);
            if (l0) *sdp = fx;
            sdp += 8;
            pA0 = oA0; pA1 = oA1; pA2 = oA2; pB0 = oB0; pB1 = oB1; pB2 = oB2;
            w2 += 12;
        }

        // ---- layer boundary: exchange partial sums, boundary diff ----
        u64* X = xch + l * XCH_PER_LAYER;
        if (!high) {
            X[i]        = aA0; X[128 + i]  = aA1; X[256 + i]  = aA2;
            X[384 + i]  = aB0; X[512 + i]  = aB1; X[640 + i]  = aB2;
            X[1536 + i] = pA0; X[1664 + i] = pA1; X[1792 + i] = pA2;
            X[1920 + i] = pB0; X[2048 + i] = pB1; X[2176 + i] = pB2;
        } else {
            X[768 + i]  = aA0; X[896 + i]  = aA1; X[1024 + i] = aA2;
            X[1152 + i] = aB0; X[1280 + i] = aB1; X[1408 + i] = aB2;
        }
        __syncthreads();
        if (!high) {
            SA0 = add2(aA0, X[768 + i]);  SA1 = add2(aA1, X[896 + i]);
            SA2 = add2(aA2, X[1024 + i]); SB0 = add2(aB0, X[1152 + i]);
            SB1 = add2(aB1, X[1280 + i]); SB2 = add2(aB2, X[1408 + i]);
        } else {
            SA0 = add2(X[i], aA0);        SA1 = add2(X[128 + i], aA1);
            SA2 = add2(X[256 + i], aA2);  SB0 = add2(X[384 + i], aB0);
            SB1 = add2(X[512 + i], aB1);  SB2 = add2(X[640 + i], aB2);
            // boundary diff: |out_half - out_{half-1}|
            u64 e0 = fma2(X[1536 + i], NEG1, fA0), e1 = fma2(X[1664 + i], NEG1, fA1),
                e2 = fma2(X[1792 + i], NEG1, fA2), e3 = fma2(X[1920 + i], NEG1, fB0),
                e4 = fma2(X[2048 + i], NEG1, fB1), e5 = fma2(X[2176 + i], NEG1, fB2);
            u64 t0 = add2(abs2(e0), abs2(e3));
            u64 t1 = add2(abs2(e1), abs2(e4));
            u64 t2 = add2(abs2(e2), abs2(e5));
            u64 tt = add2(add2(t0, t1), t2);
            u32 fx = __float2uint_rn(habs(tt) * 65536.0f);
            fx = __reduce_add_sync(0xffffffffu, fx);
            if (l0) sdiff[(blkbase + half) * 8 + wid] = fx;
        }
        blkbase += n;
        wl += n * 24;
    }

    // S3 write (low warps hold the final S; rows 4g..4g+3)
    if (!high) {
        float a0l, a0h, a1l, a1h, a2l, a2h, b0l, b0h, b1l, b1h, b2l, b2h;
        upk2(SA0, a0l, a0h); upk2(SA1, a1l, a1h); upk2(SA2, a2l, a2h);
        upk2(SB0, b0l, b0h); upk2(SB1, b1l, b1h); upk2(SB2, b2l, b2h);
        float4* op = (float4*)g_S3 + 3 * g;
        op[0] = make_float4(a0l, a1l, a2l, a0h);
        op[1] = make_float4(a1h, a2h, b0l, b1l);
        op[2] = make_float4(b2l, b0h, b1h, b2h);
    }

    // export per-CTA diff partials
    __syncthreads();
    for (int d = tid; d < NBLK; d += 256) {
        u32 s = 0;
        #pragma unroll
        for (int ww = 0; ww < 8; ww++) s += sdiff[d * 8 + ww];
        g_dpart[d * MAIN_CTAS + blockIdx.x] = s;
    }
}

// ---------------------------------------------------------------------------
// Epilogue: 1024 CTAs x 192 thr. Thread owns one c-column (M in registers),
// loops 16 rows; warp lanes = consecutive c -> contiguous stores, uniform
// s-loads. First 87 CTAs also produce the 518 stability outputs.
// ---------------------------------------------------------------------------
__global__ void __launch_bounds__(192) out_kernel(const float* __restrict__ bfin,
                                                  float* __restrict__ out) {
    const int t = threadIdx.x;

    // ---- stability outputs ----
    const int gw = blockIdx.x * 6 + (t >> 5);
    if (gw < NBLK) {
        const int lane = t & 31;
        u64 s = 0;
        #pragma unroll
        for (int k = 0; k < 4; k++)
            s += (u64)__ldg(&g_dpart[gw * MAIN_CTAS + lane + k * 32]);
        #pragma unroll
        for (int o = 16; o; o >>= 1) s += __shfl_xor_sync(0xffffffffu, s, o);
        if (lane == 0) {
            bool first = (gw == 0) | (gw == 2) | (gw == 14) | (gw == 86);
            float val = 1.0f;
            if (!first) {
                double mean = (double)s * (1.0 / (65536.0 * 65536.0 * 3.0));
                double v = 1.0 - mean;
                val = (float)(v > 0.0 ? v : 0.0);
            }
            out[OUT_STAB_OFF + gw] = val;
        }
    }

    const int c  = t % 48;
    const int rg = t / 48;                 // 0..3
    const bool act = (c < 45);
    float4 m0, m1, m2, b4;
    if (act) {
        m0 = __ldg((const float4*)(g_M) + c);
        m1 = __ldg((const float4*)(g_M + 180) + c);
        m2 = __ldg((const float4*)(g_M + 360) + c);
        b4 = __ldg((const float4*)bfin + c);
    }
    const int base = blockIdx.x * 64 + rg * 16;
    #pragma unroll 4
    for (int it = 0; it < 16; it++) {
        int r = base + it;
        float s0 = __ldg(&g_S3[r * 3 + 0]);
        float s1 = __ldg(&g_S3[r * 3 + 1]);
        float s2 = __ldg(&g_S3[r * 3 + 2]);
        if (act) {
            float4 o4;
            o4.x = fmaf(s0, m0.x, fmaf(s1, m1.x, fmaf(s2, m2.x, b4.x)));
            o4.y = fmaf(s0, m0.y, fmaf(s1, m1.y, fmaf(s2, m2.y, b4.y)));
            o4.z = fmaf(s0, m0.z, fmaf(s1, m1.z, fmaf(s2, m2.z, b4.z)));
            o4.w = fmaf(s0, m0.w, fmaf(s1, m1.w, fmaf(s2, m2.w, b4.w)));
            ((float4*)out)[r * 45 + c] = o4;
        }
    }
}

extern "C" void kernel_launch(void* const* d_in, const int* in_sizes, int n_in,
                              void* d_out, int out_size) {
    const float* x    = (const float*)d_in[0];
    const float* Wl   = (const float*)d_in[1];
    const float* Wi   = (const float*)d_in[2];
    const float* W1_0 = (const float*)d_in[3];
    const float* b1_0 = (const float*)d_in[4];
    const float* W2_0 = (const float*)d_in[5];
    const float* b2_0 = (const float*)d_in[6];
    const float* R0   = (const float*)d_in[7];
    const float* W1_1 = (const float*)d_in[8];
    const float* b1_1 = (const float*)d_in[9];
    const float* W2_1 = (const float*)d_in[10];
    const float* b2_1 = (const float*)d_in[11];
    const float* R1   = (const float*)d_in[12];
    const float* W1_2 = (const float*)d_in[13];
    const float* b1_2 = (const float*)d_in[14];
    const float* W2_2 = (const float*)d_in[15];
    const float* b2_2 = (const float*)d_in[16];
    const float* R2   = (const float*)d_in[17];
    const float* W1_3 = (const float*)d_in[18];
    const float* b1_3 = (const float*)d_in[19];
    const float* W2_3 = (const float*)d_in[20];
    const float* b2_3 = (const float*)d_in[21];
    const float* R3   = (const float*)d_in[22];
    const float* Wf   = (const float*)d_in[23];
    const float* bf   = (const float*)d_in[24];

    cudaFuncSetAttribute(main_kernel, cudaFuncAttributeMaxDynamicSharedMemorySize, MAIN_SMEM);

    s1_kernel<<<SEED_CTAS + 1 + 108, 128, S1_SMEM>>>(x, Wl, Wi, R0, R1, R2, R3);
    s2_kernel<<<13, 256>>>(Wf,
        W1_0, b1_0, W2_0, b2_0,
        W1_1, b1_1, W2_1, b2_1,
        W1_2, b1_2, W2_2, b2_2,
        W1_3, b1_3, W2_3, b2_3);
    main_kernel<<<MAIN_CTAS, 256, MAIN_SMEM>>>();
    out_kernel<<<1024, 192>>>(bf, (float*)d_out);
}